// round 1
// baseline (speedup 1.0000x reference)
#include <cuda_runtime.h>
#include <cstdint>
#include <cstddef>

// ---------------------------------------------------------------------------
// Problem constants
// ---------------------------------------------------------------------------
#define Bq   32
#define Tq   512
#define Dq   1024
#define Vq   256
#define Mq   (Bq * Tq)      // 16384 rows
#define G3   (3 * Dq)       // 3072 gate rows

// ---------------------------------------------------------------------------
// Scratch (static device arrays; no allocation allowed)
// ---------------------------------------------------------------------------
__device__ float g_act0[(size_t)Mq * Dq];          // 64 MB
__device__ float g_act1[(size_t)Mq * Dq];          // 64 MB
__device__ float g_xg[(size_t)Mq * G3];            // 192 MB
__device__ float g_h[2][Bq * Dq];                  // double-buffered hidden state
__device__ unsigned g_bar_count;
__device__ unsigned g_bar_gen;
__device__ int g_x_is64;

// ---------------------------------------------------------------------------
// GRU recurrent kernel configuration
// ---------------------------------------------------------------------------
#define GRU_NBLK    128
#define GRU_THREADS 256
#define WS_PITCH    1028                 // 1024 + 4 pad (floats)
#define HS_PITCH    132                  // 128 + 4 pad (floats)
#define GRU_SMEM_FLOATS (24 * WS_PITCH + 2 * 32 * HS_PITCH + 24 * 32 + 32)
#define GRU_SMEM_BYTES  (GRU_SMEM_FLOATS * 4)

// ---------------------------------------------------------------------------
// Grid-wide barrier (all GRU_NBLK blocks co-resident: 1 CTA/SM via smem)
// ---------------------------------------------------------------------------
__device__ __forceinline__ void grid_barrier(unsigned &mygen) {
    __threadfence();
    __syncthreads();
    if (threadIdx.x == 0) {
        unsigned old = atomicAdd(&g_bar_count, 1u);
        if (old == GRU_NBLK - 1) {
            atomicExch(&g_bar_count, 0u);
            __threadfence();
            atomicAdd(&g_bar_gen, 1u);
        } else {
            while (*((volatile unsigned *)&g_bar_gen) == mygen) { }
        }
    }
    mygen += 1u;
    __syncthreads();
}

// ---------------------------------------------------------------------------
// int64-vs-int32 token dtype detection (JAX x64 flag ambiguity)
// ---------------------------------------------------------------------------
__global__ void detect_kernel(const unsigned * __restrict__ xw) {
    if (threadIdx.x == 0 && blockIdx.x == 0) {
        int is64 = 1;
        for (int i = 1; i < 128; i += 2) {
            if (xw[i] != 0u) { is64 = 0; break; }
        }
        g_x_is64 = is64;
    }
}

// ---------------------------------------------------------------------------
// Embedding lookup: g_act0[row] = E[x[row]]
// ---------------------------------------------------------------------------
__global__ __launch_bounds__(256) void embed_kernel(const void * __restrict__ xin,
                                                    const float * __restrict__ E) {
    const int row = blockIdx.x;
    int tok;
    if (g_x_is64) tok = (int)(((const long long *)xin)[row]);
    else          tok = ((const int *)xin)[row];
    const float4 *src = (const float4 *)(E + (size_t)tok * Dq);
    float4 *dst = (float4 *)(g_act0 + (size_t)row * Dq);
    dst[threadIdx.x] = src[threadIdx.x];   // 256 threads * 4 floats = 1024
}

// ---------------------------------------------------------------------------
// Tiled fp32 NT GEMM: C[M,N] = A[M,K] * W[N,K]^T (+ bias[N])
// BM=BN=128, BK=16, 256 threads, 8x8 microtile (split 4+4 for conflict-free LDS)
// M,N divisible by 128; K divisible by 16.
// ---------------------------------------------------------------------------
__global__ __launch_bounds__(256) void sgemm_nt(const float * __restrict__ A,
                                                const float * __restrict__ W,
                                                const float * __restrict__ bias,
                                                float * __restrict__ C,
                                                int M, int N, int K) {
    __shared__ float As[16][132];
    __shared__ float Ws[16][132];

    const int bm = blockIdx.y * 128;
    const int bn = blockIdx.x * 128;
    const int tid = threadIdx.x;
    const int tx = tid & 15;            // column group
    const int ty = tid >> 4;            // row group
    const int lr = tid >> 2;            // loader row 0..63
    const int lc = (tid & 3) << 2;      // loader col 0,4,8,12

    float acc[8][8];
#pragma unroll
    for (int i = 0; i < 8; ++i)
#pragma unroll
        for (int j = 0; j < 8; ++j) acc[i][j] = 0.f;

    const float *Ap = A + (size_t)(bm + lr) * K + lc;
    const float *Wp = W + (size_t)(bn + lr) * K + lc;
    const size_t half = (size_t)64 * K;

    for (int k0 = 0; k0 < K; k0 += 16) {
        float4 a0 = *(const float4 *)(Ap + k0);
        float4 a1 = *(const float4 *)(Ap + half + k0);
        float4 w0 = *(const float4 *)(Wp + k0);
        float4 w1 = *(const float4 *)(Wp + half + k0);
        __syncthreads();
        As[lc + 0][lr] = a0.x; As[lc + 1][lr] = a0.y; As[lc + 2][lr] = a0.z; As[lc + 3][lr] = a0.w;
        As[lc + 0][lr + 64] = a1.x; As[lc + 1][lr + 64] = a1.y; As[lc + 2][lr + 64] = a1.z; As[lc + 3][lr + 64] = a1.w;
        Ws[lc + 0][lr] = w0.x; Ws[lc + 1][lr] = w0.y; Ws[lc + 2][lr] = w0.z; Ws[lc + 3][lr] = w0.w;
        Ws[lc + 0][lr + 64] = w1.x; Ws[lc + 1][lr + 64] = w1.y; Ws[lc + 2][lr + 64] = w1.z; Ws[lc + 3][lr + 64] = w1.w;
        __syncthreads();
#pragma unroll
        for (int kk = 0; kk < 16; ++kk) {
            float af[8], wf[8];
            *(float4 *)&af[0] = *(const float4 *)&As[kk][ty * 4];
            *(float4 *)&af[4] = *(const float4 *)&As[kk][64 + ty * 4];
            *(float4 *)&wf[0] = *(const float4 *)&Ws[kk][tx * 4];
            *(float4 *)&wf[4] = *(const float4 *)&Ws[kk][64 + tx * 4];
#pragma unroll
            for (int i = 0; i < 8; ++i)
#pragma unroll
                for (int j = 0; j < 8; ++j) acc[i][j] += af[i] * wf[j];
        }
    }

    // bias fragments
    float bf[8];
#pragma unroll
    for (int j = 0; j < 8; ++j) {
        int col = bn + ((j < 4) ? (tx * 4 + j) : (64 + tx * 4 + j - 4));
        bf[j] = bias ? bias[col] : 0.f;
    }

#pragma unroll
    for (int i = 0; i < 8; ++i) {
        int row = bm + ((i < 4) ? (ty * 4 + i) : (64 + ty * 4 + i - 4));
        float4 v0, v1;
        v0.x = acc[i][0] + bf[0]; v0.y = acc[i][1] + bf[1];
        v0.z = acc[i][2] + bf[2]; v0.w = acc[i][3] + bf[3];
        v1.x = acc[i][4] + bf[4]; v1.y = acc[i][5] + bf[5];
        v1.z = acc[i][6] + bf[6]; v1.w = acc[i][7] + bf[7];
        *(float4 *)&C[(size_t)row * N + bn + tx * 4] = v0;
        *(float4 *)&C[(size_t)row * N + bn + 64 + tx * 4] = v1;
    }
}

// ---------------------------------------------------------------------------
// Persistent GRU recurrent scan over T=512 steps.
// Block `blk` owns dims d0..d0+7 (all 3 gates, all 32 batches).
// Whh slice (24 x 1024, 96 KB) stays in smem for the whole sequence.
// h is double-buffered in global; staged into smem in 128-k chunks with
// register prefetch double-buffering. 16-way k-split + shfl reduce.
// ---------------------------------------------------------------------------
__global__ __launch_bounds__(GRU_THREADS, 1) void gru_recur(
        const float * __restrict__ Whh, const float * __restrict__ bhh,
        float * __restrict__ outp) {
    extern __shared__ float smem[];
    float *w_s  = smem;                          // [24][WS_PITCH]
    float *h_s  = w_s + 24 * WS_PITCH;           // [2][32][HS_PITCH]
    float *hg_s = h_s + 2 * 32 * HS_PITCH;       // [24][32]
    float *bh_s = hg_s + 24 * 32;                // [24]

    const int tid = threadIdx.x;
    const int blk = blockIdx.x;
    const int d0  = blk * 8;

    // Load weight slice: rows g*8+dd map to Whh row (g*Dq + d0 + dd)
    for (int i = tid; i < 24 * 256; i += GRU_THREADS) {
        int r = i >> 8;            // 0..23
        int c4 = i & 255;          // 0..255 (float4 index)
        int g = r >> 3, dd = r & 7;
        float4 v = *(const float4 *)&Whh[(size_t)(g * Dq + d0 + dd) * Dq + (c4 << 2)];
        *(float4 *)&w_s[r * WS_PITCH + (c4 << 2)] = v;
    }
    if (tid < 24) bh_s[tid] = bhh[(tid >> 3) * Dq + d0 + (tid & 7)];

    // Zero this block's slice of both h buffers
    for (int i = tid; i < 2 * 32 * 8; i += GRU_THREADS) {
        int buf = (i >= 256) ? 1 : 0;
        int j = i & 255;
        int b = j >> 3, dd = j & 7;
        g_h[buf][b * Dq + d0 + dd] = 0.f;
    }

    unsigned mygen = *((volatile unsigned *)&g_bar_gen);
    grid_barrier(mygen);

    const int lane = tid & 31;
    const int ks   = lane & 15;                        // 16-way k-split
    const int pos  = (tid >> 5) * 2 + (lane >> 4);     // 0..15
    const int b0   = (pos & 3) * 8;                    // batch base (8 batches)
    const int dloc0 = (pos >> 2) * 2;                  // local dim base (2 dims)

    // staging indices (4 float4 per thread per chunk)
    int sb[4], sc4[4];
#pragma unroll
    for (int j = 0; j < 4; ++j) {
        int i = tid + j * GRU_THREADS;
        sb[j] = i >> 5;      // batch row 0..31
        sc4[j] = i & 31;     // float4 col within 128-k chunk
    }

    for (int t = 0; t < Tq; ++t) {
        const float *hin  = g_h[t & 1];
        float       *hout = g_h[(t + 1) & 1];

        // stage chunk 0 into buffer 0
#pragma unroll
        for (int j = 0; j < 4; ++j) {
            float4 v = __ldcg((const float4 *)&hin[sb[j] * Dq + (sc4[j] << 2)]);
            *(float4 *)&h_s[sb[j] * HS_PITCH + (sc4[j] << 2)] = v;
        }
        __syncthreads();

        float acc[3][2][8];
#pragma unroll
        for (int g = 0; g < 3; ++g)
#pragma unroll
            for (int dd = 0; dd < 2; ++dd)
#pragma unroll
                for (int bb = 0; bb < 8; ++bb) acc[g][dd][bb] = 0.f;

        int p = 0;
        for (int c = 0; c < 8; ++c) {
            float4 nx[4];
            if (c < 7) {
#pragma unroll
                for (int j = 0; j < 4; ++j)
                    nx[j] = __ldcg((const float4 *)&hin[sb[j] * Dq + (c + 1) * 128 + (sc4[j] << 2)]);
            }
            const float *hb = h_s + p * 32 * HS_PITCH;
#pragma unroll
            for (int j4 = 0; j4 < 2; ++j4) {
                const int kk = j4 * 64 + ks * 4;   // conflict-free stride
                float4 hv[8];
#pragma unroll
                for (int bb = 0; bb < 8; ++bb)
                    hv[bb] = *(const float4 *)&hb[(b0 + bb) * HS_PITCH + kk];
#pragma unroll
                for (int g = 0; g < 3; ++g) {
#pragma unroll
                    for (int dd = 0; dd < 2; ++dd) {
                        float4 wv = *(const float4 *)&w_s[(g * 8 + dloc0 + dd) * WS_PITCH + c * 128 + kk];
#pragma unroll
                        for (int bb = 0; bb < 8; ++bb) {
                            acc[g][dd][bb] += wv.x * hv[bb].x;
                            acc[g][dd][bb] += wv.y * hv[bb].y;
                            acc[g][dd][bb] += wv.z * hv[bb].z;
                            acc[g][dd][bb] += wv.w * hv[bb].w;
                        }
                    }
                }
            }
            if (c < 7) {
                float *hn = h_s + (p ^ 1) * 32 * HS_PITCH;
#pragma unroll
                for (int j = 0; j < 4; ++j)
                    *(float4 *)&hn[sb[j] * HS_PITCH + (sc4[j] << 2)] = nx[j];
            }
            __syncthreads();
            p ^= 1;
        }

        // reduce across the 16 k-split lanes (xor groups aligned to 16)
#pragma unroll
        for (int off = 8; off; off >>= 1) {
#pragma unroll
            for (int g = 0; g < 3; ++g)
#pragma unroll
                for (int dd = 0; dd < 2; ++dd)
#pragma unroll
                    for (int bb = 0; bb < 8; ++bb)
                        acc[g][dd][bb] += __shfl_xor_sync(0xffffffffu, acc[g][dd][bb], off);
        }
        if (ks == 0) {
#pragma unroll
            for (int g = 0; g < 3; ++g)
#pragma unroll
                for (int dd = 0; dd < 2; ++dd)
#pragma unroll
                    for (int bb = 0; bb < 8; ++bb)
                        hg_s[(g * 8 + dloc0 + dd) * 32 + b0 + bb] = acc[g][dd][bb];
        }
        __syncthreads();

        // activation + state update: thread -> (b = tid>>3, dd = tid&7)
        {
            const int b = tid >> 3, dd = tid & 7;
            const int dg = d0 + dd;
            const size_t xb = ((size_t)b * Tq + t) * G3 + dg;
            float xr = __ldg(&g_xg[xb]);
            float xz = __ldg(&g_xg[xb + Dq]);
            float xn = __ldg(&g_xg[xb + 2 * Dq]);
            float hr = hg_s[(0 * 8 + dd) * 32 + b] + bh_s[dd];
            float hz = hg_s[(1 * 8 + dd) * 32 + b] + bh_s[8 + dd];
            float hn2 = hg_s[(2 * 8 + dd) * 32 + b] + bh_s[16 + dd];
            float hold = __ldcg(&hin[b * Dq + dg]);
            float r = 1.f / (1.f + expf(-(xr + hr)));
            float z = 1.f / (1.f + expf(-(xz + hz)));
            float n = tanhf(xn + r * hn2);
            float hnew = (1.f - z) * n + z * hold;
            __stcg(&hout[b * Dq + dg], hnew);
            outp[((size_t)b * Tq + t) * Dq + dg] = hnew;
        }
        grid_barrier(mygen);
    }
}

// ---------------------------------------------------------------------------
// LayerNorm over last dim (1024), one block per row
// ---------------------------------------------------------------------------
__global__ __launch_bounds__(256) void ln_kernel(const float * __restrict__ in,
                                                 float * __restrict__ outp,
                                                 const float * __restrict__ gamma,
                                                 const float * __restrict__ beta) {
    __shared__ float red[2][8];
    const int row = blockIdx.x;
    const int tid = threadIdx.x;
    float4 x = *(const float4 *)&in[(size_t)row * Dq + tid * 4];
    float s = x.x + x.y + x.z + x.w;
    float q = x.x * x.x + x.y * x.y + x.z * x.z + x.w * x.w;
#pragma unroll
    for (int off = 16; off; off >>= 1) {
        s += __shfl_xor_sync(0xffffffffu, s, off);
        q += __shfl_xor_sync(0xffffffffu, q, off);
    }
    if ((tid & 31) == 0) { red[0][tid >> 5] = s; red[1][tid >> 5] = q; }
    __syncthreads();
    if (tid < 32) {
        float ss = (tid < 8) ? red[0][tid] : 0.f;
        float qq = (tid < 8) ? red[1][tid] : 0.f;
#pragma unroll
        for (int off = 4; off; off >>= 1) {
            ss += __shfl_xor_sync(0xffffffffu, ss, off);
            qq += __shfl_xor_sync(0xffffffffu, qq, off);
        }
        if (tid == 0) { red[0][0] = ss; red[1][0] = qq; }
    }
    __syncthreads();
    const float mean = red[0][0] * (1.f / Dq);
    const float var = red[1][0] * (1.f / Dq) - mean * mean;
    const float inv = rsqrtf(var + 1e-5f);
    float4 g  = *(const float4 *)&gamma[tid * 4];
    float4 be = *(const float4 *)&beta[tid * 4];
    float4 o;
    o.x = (x.x - mean) * inv * g.x + be.x;
    o.y = (x.y - mean) * inv * g.y + be.y;
    o.z = (x.z - mean) * inv * g.z + be.z;
    o.w = (x.w - mean) * inv * g.w + be.w;
    *(float4 *)&outp[(size_t)row * Dq + tid * 4] = o;
}

// ---------------------------------------------------------------------------
// Host driver
// Inputs (metadata order): x, E, Wih, Whh, bih, bhh, gamma, beta
// Output: logits f32 [32, 512, 256]
// ---------------------------------------------------------------------------
extern "C" void kernel_launch(void *const *d_in, const int *in_sizes, int n_in,
                              void *d_out, int out_size) {
    (void)in_sizes; (void)n_in; (void)out_size;
    const void  *x     = d_in[0];
    const float *E     = (const float *)d_in[1];
    const float *Wih   = (const float *)d_in[2];
    const float *Whh   = (const float *)d_in[3];
    const float *bih   = (const float *)d_in[4];
    const float *bhh   = (const float *)d_in[5];
    const float *gamma = (const float *)d_in[6];
    const float *beta  = (const float *)d_in[7];
    float *out = (float *)d_out;

    float *act0 = nullptr, *act1 = nullptr, *xg = nullptr;
    cudaGetSymbolAddress((void **)&act0, g_act0);
    cudaGetSymbolAddress((void **)&act1, g_act1);
    cudaGetSymbolAddress((void **)&xg, g_xg);

    cudaFuncSetAttribute(gru_recur, cudaFuncAttributeMaxDynamicSharedMemorySize,
                         GRU_SMEM_BYTES);

    detect_kernel<<<1, 32>>>((const unsigned *)x);
    embed_kernel<<<Mq, 256>>>(x, E);

    dim3 gx(G3 / 128, Mq / 128);
    // layer 0
    sgemm_nt<<<gx, 256>>>(act0, Wih, bih, xg, Mq, G3, Dq);
    gru_recur<<<GRU_NBLK, GRU_THREADS, GRU_SMEM_BYTES>>>(Whh, bhh, act1);
    // layer 1
    sgemm_nt<<<gx, 256>>>(act1, Wih + (size_t)G3 * Dq, bih + G3, xg, Mq, G3, Dq);
    gru_recur<<<GRU_NBLK, GRU_THREADS, GRU_SMEM_BYTES>>>(Whh + (size_t)G3 * Dq,
                                                         bhh + G3, act0);
    // LayerNorm + tied head
    ln_kernel<<<Mq, 256>>>(act0, act1, gamma, beta);
    dim3 gh(Vq / 128, Mq / 128);
    sgemm_nt<<<gh, 256>>>(act1, E, nullptr, out, Mq, Vq, Dq);
}

// round 2
// speedup vs baseline: 1.1685x; 1.1685x over previous
#include <cuda_runtime.h>
#include <cstdint>
#include <cstddef>

// ---------------------------------------------------------------------------
// Problem constants
// ---------------------------------------------------------------------------
#define Bq   32
#define Tq   512
#define Dq   1024
#define Vq   256
#define Mq   (Bq * Tq)      // 16384 rows
#define G3   (3 * Dq)       // 3072 gate rows

// ---------------------------------------------------------------------------
// Scratch (static device arrays; no allocation allowed)
// ---------------------------------------------------------------------------
__device__ float g_act0[(size_t)Mq * Dq];          // 64 MB
__device__ float g_act1[(size_t)Mq * Dq];          // 64 MB
__device__ float g_xg[(size_t)Mq * G3];            // 192 MB (layer-1 gates)
__device__ float g_tab[(size_t)Vq * G3];           // 3 MB  (layer-0 gate table)
__device__ float g_h[2][Bq * Dq];                  // double-buffered hidden state
__device__ unsigned g_bar_count;
__device__ unsigned g_bar_gen;
__device__ int g_x_is64;

// ---------------------------------------------------------------------------
// GRU recurrent kernel configuration
// ---------------------------------------------------------------------------
#define GRU_NBLK    128
#define GRU_THREADS 256
#define WS_PITCH    1028                 // 1024 + 4 pad (floats)
#define HS_PITCH    132                  // 128 + 4 pad (floats)
#define GRU_SMEM_FLOATS (24 * WS_PITCH + 2 * 32 * HS_PITCH + 24 * 32 + 32)
#define GRU_SMEM_BYTES  (GRU_SMEM_FLOATS * 4)

// ---------------------------------------------------------------------------
// Grid-wide barrier (all GRU_NBLK blocks co-resident: 1 CTA/SM via smem)
// ---------------------------------------------------------------------------
__device__ __forceinline__ void grid_barrier(unsigned &mygen) {
    __threadfence();
    __syncthreads();
    if (threadIdx.x == 0) {
        unsigned old = atomicAdd(&g_bar_count, 1u);
        if (old == GRU_NBLK - 1) {
            atomicExch(&g_bar_count, 0u);
            __threadfence();
            atomicAdd(&g_bar_gen, 1u);
        } else {
            while (*((volatile unsigned *)&g_bar_gen) == mygen) { }
        }
    }
    mygen += 1u;
    __syncthreads();
}

// ---------------------------------------------------------------------------
// int64-vs-int32 token dtype detection (JAX x64 flag ambiguity)
// ---------------------------------------------------------------------------
__global__ void detect_kernel(const unsigned * __restrict__ xw) {
    if (threadIdx.x == 0 && blockIdx.x == 0) {
        int is64 = 1;
        for (int i = 1; i < 128; i += 2) {
            if (xw[i] != 0u) { is64 = 0; break; }
        }
        g_x_is64 = is64;
    }
}

// ---------------------------------------------------------------------------
// Tiled fp32 NT GEMM: C[M,N] = A[M,K] * W[N,K]^T (+ bias[N])
// BM=BN=128, BK=16, 256 threads, 8x8 microtile (split 4+4 for conflict-free LDS)
// M,N divisible by 128; K divisible by 16.
// ---------------------------------------------------------------------------
__global__ __launch_bounds__(256) void sgemm_nt(const float * __restrict__ A,
                                                const float * __restrict__ W,
                                                const float * __restrict__ bias,
                                                float * __restrict__ C,
                                                int M, int N, int K) {
    __shared__ float As[16][132];
    __shared__ float Ws[16][132];

    const int bm = blockIdx.y * 128;
    const int bn = blockIdx.x * 128;
    const int tid = threadIdx.x;
    const int tx = tid & 15;            // column group
    const int ty = tid >> 4;            // row group
    const int lr = tid >> 2;            // loader row 0..63
    const int lc = (tid & 3) << 2;      // loader col 0,4,8,12

    float acc[8][8];
#pragma unroll
    for (int i = 0; i < 8; ++i)
#pragma unroll
        for (int j = 0; j < 8; ++j) acc[i][j] = 0.f;

    const float *Ap = A + (size_t)(bm + lr) * K + lc;
    const float *Wp = W + (size_t)(bn + lr) * K + lc;
    const size_t half = (size_t)64 * K;

    for (int k0 = 0; k0 < K; k0 += 16) {
        float4 a0 = *(const float4 *)(Ap + k0);
        float4 a1 = *(const float4 *)(Ap + half + k0);
        float4 w0 = *(const float4 *)(Wp + k0);
        float4 w1 = *(const float4 *)(Wp + half + k0);
        __syncthreads();
        As[lc + 0][lr] = a0.x; As[lc + 1][lr] = a0.y; As[lc + 2][lr] = a0.z; As[lc + 3][lr] = a0.w;
        As[lc + 0][lr + 64] = a1.x; As[lc + 1][lr + 64] = a1.y; As[lc + 2][lr + 64] = a1.z; As[lc + 3][lr + 64] = a1.w;
        Ws[lc + 0][lr] = w0.x; Ws[lc + 1][lr] = w0.y; Ws[lc + 2][lr] = w0.z; Ws[lc + 3][lr] = w0.w;
        Ws[lc + 0][lr + 64] = w1.x; Ws[lc + 1][lr + 64] = w1.y; Ws[lc + 2][lr + 64] = w1.z; Ws[lc + 3][lr + 64] = w1.w;
        __syncthreads();
#pragma unroll
        for (int kk = 0; kk < 16; ++kk) {
            float af[8], wf[8];
            *(float4 *)&af[0] = *(const float4 *)&As[kk][ty * 4];
            *(float4 *)&af[4] = *(const float4 *)&As[kk][64 + ty * 4];
            *(float4 *)&wf[0] = *(const float4 *)&Ws[kk][tx * 4];
            *(float4 *)&wf[4] = *(const float4 *)&Ws[kk][64 + tx * 4];
#pragma unroll
            for (int i = 0; i < 8; ++i)
#pragma unroll
                for (int j = 0; j < 8; ++j) acc[i][j] += af[i] * wf[j];
        }
    }

    // bias fragments
    float bf[8];
#pragma unroll
    for (int j = 0; j < 8; ++j) {
        int col = bn + ((j < 4) ? (tx * 4 + j) : (64 + tx * 4 + j - 4));
        bf[j] = bias ? bias[col] : 0.f;
    }

#pragma unroll
    for (int i = 0; i < 8; ++i) {
        int row = bm + ((i < 4) ? (ty * 4 + i) : (64 + ty * 4 + i - 4));
        float4 v0, v1;
        v0.x = acc[i][0] + bf[0]; v0.y = acc[i][1] + bf[1];
        v0.z = acc[i][2] + bf[2]; v0.w = acc[i][3] + bf[3];
        v1.x = acc[i][4] + bf[4]; v1.y = acc[i][5] + bf[5];
        v1.z = acc[i][6] + bf[6]; v1.w = acc[i][7] + bf[7];
        *(float4 *)&C[(size_t)row * N + bn + tx * 4] = v0;
        *(float4 *)&C[(size_t)row * N + bn + 64 + tx * 4] = v1;
    }
}

// ---------------------------------------------------------------------------
// Persistent GRU recurrent scan over T=512 steps.
// Block `blk` owns dims d0..d0+7 (all 3 gates, all 32 batches).
// Whh slice (24 x 1024, 96 KB) stays in smem for the whole sequence.
// h is double-buffered in global; staged into smem in 128-k chunks with
// register prefetch double-buffering. 16-way k-split + shfl reduce.
//
// Input gates: if `tokens` is non-null, xg comes from the per-vocab gate
// table `xgv` indexed by token (layer 0: xg = (E @ Wih^T + bih)[x]).
// Otherwise xgv is a dense [B,T,3D] tensor (layer 1).
// ---------------------------------------------------------------------------
__global__ __launch_bounds__(GRU_THREADS, 1) void gru_recur(
        const float * __restrict__ Whh, const float * __restrict__ bhh,
        const float * __restrict__ xgv, const void * __restrict__ tokens,
        float * __restrict__ outp) {
    extern __shared__ float smem[];
    float *w_s  = smem;                          // [24][WS_PITCH]
    float *h_s  = w_s + 24 * WS_PITCH;           // [2][32][HS_PITCH]
    float *hg_s = h_s + 2 * 32 * HS_PITCH;       // [24][32]
    float *bh_s = hg_s + 24 * 32;                // [24]

    const int tid = threadIdx.x;
    const int blk = blockIdx.x;
    const int d0  = blk * 8;

    // Load weight slice: rows g*8+dd map to Whh row (g*Dq + d0 + dd)
    for (int i = tid; i < 24 * 256; i += GRU_THREADS) {
        int r = i >> 8;            // 0..23
        int c4 = i & 255;          // 0..255 (float4 index)
        int g = r >> 3, dd = r & 7;
        float4 v = *(const float4 *)&Whh[(size_t)(g * Dq + d0 + dd) * Dq + (c4 << 2)];
        *(float4 *)&w_s[r * WS_PITCH + (c4 << 2)] = v;
    }
    if (tid < 24) bh_s[tid] = bhh[(tid >> 3) * Dq + d0 + (tid & 7)];

    // Zero this block's slice of both h buffers
    for (int i = tid; i < 2 * 32 * 8; i += GRU_THREADS) {
        int buf = (i >= 256) ? 1 : 0;
        int j = i & 255;
        int b = j >> 3, dd = j & 7;
        g_h[buf][b * Dq + d0 + dd] = 0.f;
    }

    unsigned mygen = *((volatile unsigned *)&g_bar_gen);
    grid_barrier(mygen);

    const int x64 = g_x_is64;
    const int lane = tid & 31;
    const int ks   = lane & 15;                        // 16-way k-split
    const int pos  = (tid >> 5) * 2 + (lane >> 4);     // 0..15
    const int b0   = (pos & 3) * 8;                    // batch base (8 batches)
    const int dloc0 = (pos >> 2) * 2;                  // local dim base (2 dims)

    // staging indices (4 float4 per thread per chunk)
    int sb[4], sc4[4];
#pragma unroll
    for (int j = 0; j < 4; ++j) {
        int i = tid + j * GRU_THREADS;
        sb[j] = i >> 5;      // batch row 0..31
        sc4[j] = i & 31;     // float4 col within 128-k chunk
    }

    for (int t = 0; t < Tq; ++t) {
        const float *hin  = g_h[t & 1];
        float       *hout = g_h[(t + 1) & 1];

        // stage chunk 0 into buffer 0
#pragma unroll
        for (int j = 0; j < 4; ++j) {
            float4 v = __ldcg((const float4 *)&hin[sb[j] * Dq + (sc4[j] << 2)]);
            *(float4 *)&h_s[sb[j] * HS_PITCH + (sc4[j] << 2)] = v;
        }
        __syncthreads();

        float acc[3][2][8];
#pragma unroll
        for (int g = 0; g < 3; ++g)
#pragma unroll
            for (int dd = 0; dd < 2; ++dd)
#pragma unroll
                for (int bb = 0; bb < 8; ++bb) acc[g][dd][bb] = 0.f;

        int p = 0;
        for (int c = 0; c < 8; ++c) {
            float4 nx[4];
            if (c < 7) {
#pragma unroll
                for (int j = 0; j < 4; ++j)
                    nx[j] = __ldcg((const float4 *)&hin[sb[j] * Dq + (c + 1) * 128 + (sc4[j] << 2)]);
            }
            const float *hb = h_s + p * 32 * HS_PITCH;
#pragma unroll
            for (int j4 = 0; j4 < 2; ++j4) {
                const int kk = j4 * 64 + ks * 4;   // conflict-free stride
                float4 hv[8];
#pragma unroll
                for (int bb = 0; bb < 8; ++bb)
                    hv[bb] = *(const float4 *)&hb[(b0 + bb) * HS_PITCH + kk];
#pragma unroll
                for (int g = 0; g < 3; ++g) {
#pragma unroll
                    for (int dd = 0; dd < 2; ++dd) {
                        float4 wv = *(const float4 *)&w_s[(g * 8 + dloc0 + dd) * WS_PITCH + c * 128 + kk];
#pragma unroll
                        for (int bb = 0; bb < 8; ++bb) {
                            acc[g][dd][bb] += wv.x * hv[bb].x;
                            acc[g][dd][bb] += wv.y * hv[bb].y;
                            acc[g][dd][bb] += wv.z * hv[bb].z;
                            acc[g][dd][bb] += wv.w * hv[bb].w;
                        }
                    }
                }
            }
            if (c < 7) {
                float *hn = h_s + (p ^ 1) * 32 * HS_PITCH;
#pragma unroll
                for (int j = 0; j < 4; ++j)
                    *(float4 *)&hn[sb[j] * HS_PITCH + (sc4[j] << 2)] = nx[j];
            }
            __syncthreads();
            p ^= 1;
        }

        // reduce across the 16 k-split lanes (xor groups aligned to 16)
#pragma unroll
        for (int off = 8; off; off >>= 1) {
#pragma unroll
            for (int g = 0; g < 3; ++g)
#pragma unroll
                for (int dd = 0; dd < 2; ++dd)
#pragma unroll
                    for (int bb = 0; bb < 8; ++bb)
                        acc[g][dd][bb] += __shfl_xor_sync(0xffffffffu, acc[g][dd][bb], off);
        }
        if (ks == 0) {
#pragma unroll
            for (int g = 0; g < 3; ++g)
#pragma unroll
                for (int dd = 0; dd < 2; ++dd)
#pragma unroll
                    for (int bb = 0; bb < 8; ++bb)
                        hg_s[(g * 8 + dloc0 + dd) * 32 + b0 + bb] = acc[g][dd][bb];
        }
        __syncthreads();

        // activation + state update: thread -> (b = tid>>3, dd = tid&7)
        {
            const int b = tid >> 3, dd = tid & 7;
            const int dg = d0 + dd;
            size_t xb;
            if (tokens) {
                int tok;
                if (x64) tok = (int)(((const long long *)tokens)[b * Tq + t]);
                else     tok = ((const int *)tokens)[b * Tq + t];
                xb = (size_t)tok * G3 + dg;
            } else {
                xb = ((size_t)b * Tq + t) * G3 + dg;
            }
            float xr = __ldg(&xgv[xb]);
            float xz = __ldg(&xgv[xb + Dq]);
            float xn = __ldg(&xgv[xb + 2 * Dq]);
            float hr = hg_s[(0 * 8 + dd) * 32 + b] + bh_s[dd];
            float hz = hg_s[(1 * 8 + dd) * 32 + b] + bh_s[8 + dd];
            float hn2 = hg_s[(2 * 8 + dd) * 32 + b] + bh_s[16 + dd];
            float hold = __ldcg(&hin[b * Dq + dg]);
            float r = 1.f / (1.f + expf(-(xr + hr)));
            float z = 1.f / (1.f + expf(-(xz + hz)));
            float n = tanhf(xn + r * hn2);
            float hnew = (1.f - z) * n + z * hold;
            __stcg(&hout[b * Dq + dg], hnew);
            outp[((size_t)b * Tq + t) * Dq + dg] = hnew;
        }
        grid_barrier(mygen);
    }
}

// ---------------------------------------------------------------------------
// LayerNorm over last dim (1024), one block per row
// ---------------------------------------------------------------------------
__global__ __launch_bounds__(256) void ln_kernel(const float * __restrict__ in,
                                                 float * __restrict__ outp,
                                                 const float * __restrict__ gamma,
                                                 const float * __restrict__ beta) {
    __shared__ float red[2][8];
    const int row = blockIdx.x;
    const int tid = threadIdx.x;
    float4 x = *(const float4 *)&in[(size_t)row * Dq + tid * 4];
    float s = x.x + x.y + x.z + x.w;
    float q = x.x * x.x + x.y * x.y + x.z * x.z + x.w * x.w;
#pragma unroll
    for (int off = 16; off; off >>= 1) {
        s += __shfl_xor_sync(0xffffffffu, s, off);
        q += __shfl_xor_sync(0xffffffffu, q, off);
    }
    if ((tid & 31) == 0) { red[0][tid >> 5] = s; red[1][tid >> 5] = q; }
    __syncthreads();
    if (tid < 32) {
        float ss = (tid < 8) ? red[0][tid] : 0.f;
        float qq = (tid < 8) ? red[1][tid] : 0.f;
#pragma unroll
        for (int off = 4; off; off >>= 1) {
            ss += __shfl_xor_sync(0xffffffffu, ss, off);
            qq += __shfl_xor_sync(0xffffffffu, qq, off);
        }
        if (tid == 0) { red[0][0] = ss; red[1][0] = qq; }
    }
    __syncthreads();
    const float mean = red[0][0] * (1.f / Dq);
    const float var = red[1][0] * (1.f / Dq) - mean * mean;
    const float inv = rsqrtf(var + 1e-5f);
    float4 g  = *(const float4 *)&gamma[tid * 4];
    float4 be = *(const float4 *)&beta[tid * 4];
    float4 o;
    o.x = (x.x - mean) * inv * g.x + be.x;
    o.y = (x.y - mean) * inv * g.y + be.y;
    o.z = (x.z - mean) * inv * g.z + be.z;
    o.w = (x.w - mean) * inv * g.w + be.w;
    *(float4 *)&outp[(size_t)row * Dq + tid * 4] = o;
}

// ---------------------------------------------------------------------------
// Host driver
// Inputs (metadata order): x, E, Wih, Whh, bih, bhh, gamma, beta
// Output: logits f32 [32, 512, 256]
// ---------------------------------------------------------------------------
extern "C" void kernel_launch(void *const *d_in, const int *in_sizes, int n_in,
                              void *d_out, int out_size) {
    (void)in_sizes; (void)n_in; (void)out_size;
    const void  *x     = d_in[0];
    const float *E     = (const float *)d_in[1];
    const float *Wih   = (const float *)d_in[2];
    const float *Whh   = (const float *)d_in[3];
    const float *bih   = (const float *)d_in[4];
    const float *bhh   = (const float *)d_in[5];
    const float *gamma = (const float *)d_in[6];
    const float *beta  = (const float *)d_in[7];
    float *out = (float *)d_out;

    float *act0 = nullptr, *act1 = nullptr, *xg = nullptr, *tab = nullptr;
    cudaGetSymbolAddress((void **)&act0, g_act0);
    cudaGetSymbolAddress((void **)&act1, g_act1);
    cudaGetSymbolAddress((void **)&xg, g_xg);
    cudaGetSymbolAddress((void **)&tab, g_tab);

    cudaFuncSetAttribute(gru_recur, cudaFuncAttributeMaxDynamicSharedMemorySize,
                         GRU_SMEM_BYTES);

    detect_kernel<<<1, 32>>>((const unsigned *)x);

    // ---- layer 0: per-vocab gate table XG0[v] = E[v] @ Wih0^T + bih0 ----
    // (only 256 distinct embedding rows -> 1.6 GF instead of 103 GF)
    {
        dim3 gt(G3 / 128, Vq / 128);
        sgemm_nt<<<gt, 256>>>(E, Wih, bih, tab, Vq, G3, Dq);
    }
    gru_recur<<<GRU_NBLK, GRU_THREADS, GRU_SMEM_BYTES>>>(Whh, bhh, tab, x, act1);

    // ---- layer 1: dense input-gate GEMM over scan-0 outputs ----
    {
        dim3 gx(G3 / 128, Mq / 128);
        sgemm_nt<<<gx, 256>>>(act1, Wih + (size_t)G3 * Dq, bih + G3, xg, Mq, G3, Dq);
    }
    gru_recur<<<GRU_NBLK, GRU_THREADS, GRU_SMEM_BYTES>>>(Whh + (size_t)G3 * Dq,
                                                         bhh + G3, xg, nullptr, act0);

    // ---- LayerNorm + tied head ----
    ln_kernel<<<Mq, 256>>>(act0, act1, gamma, beta);
    dim3 gh(Vq / 128, Mq / 128);
    sgemm_nt<<<gh, 256>>>(act1, E, nullptr, out, Mq, Vq, Dq);
}

// round 5
// speedup vs baseline: 1.1781x; 1.0082x over previous
#include <cuda_runtime.h>
#include <cuda_bf16.h>
#include <cstdint>
#include <cstddef>

// ---------------------------------------------------------------------------
// Problem constants
// ---------------------------------------------------------------------------
#define Bq   32
#define Tq   512
#define Dq   1024
#define Vq   256
#define Mq   (Bq * Tq)      // 16384 rows
#define G3   (3 * Dq)       // 3072 gate rows

// ---------------------------------------------------------------------------
// Scratch (static device arrays; no allocation allowed)
// ---------------------------------------------------------------------------
__device__ float g_act0[(size_t)Mq * Dq];          // 64 MB
__device__ float g_act1[(size_t)Mq * Dq];          // 64 MB
__device__ float g_xg[(size_t)Mq * G3];            // 192 MB (layer-1 gates)
__device__ float g_tab[(size_t)Vq * G3];           // 3 MB  (layer-0 gate table)
__device__ float g_h32[Bq * Dq];                   // fp32 hidden state
__device__ __nv_bfloat16 g_hhi[Bq * Dq];           // bf16 hi part of h
__device__ __nv_bfloat16 g_hlo[Bq * Dq];           // bf16 lo part of h
__device__ float g_part[4 * G3 * Bq];              // K-quarter partials (1.5MB)
__device__ unsigned g_bar_count;
__device__ unsigned g_bar_gen;
__device__ int g_x_is64;

// ---------------------------------------------------------------------------
// Tensor-core (mma.sync) GRU config: 24 M-tiles (128 rows) x 4 K-quarters(256)
// ---------------------------------------------------------------------------
#define GRU_NBLK    96
#define GRU_THREADS 256
// smem: weight staging buffer 128 rows x 264 bf16 (528B padded stride);
// reused per-step as h-quarter B tiles (hi at 0, lo at 16896).
#define ROW_B       528
#define WBUF_BYTES  (128 * ROW_B)      // 67584
#define GRU_DYN_SMEM (WBUF_BYTES + 256)

__device__ __forceinline__ uint32_t smem_u32(const void *p) {
    uint32_t a;
    asm("{ .reg .u64 t; cvta.to.shared.u64 t, %1; cvt.u32.u64 %0, t; }"
        : "=r"(a) : "l"(p));
    return a;
}
__device__ __forceinline__ void ldmx4(uint32_t &r0, uint32_t &r1,
                                      uint32_t &r2, uint32_t &r3, uint32_t addr) {
    asm volatile("ldmatrix.sync.aligned.m8n8.x4.shared.b16 {%0,%1,%2,%3}, [%4];"
                 : "=r"(r0), "=r"(r1), "=r"(r2), "=r"(r3) : "r"(addr));
}
__device__ __forceinline__ void mma_bf16(float &c0, float &c1, float &c2, float &c3,
                                         uint32_t a0, uint32_t a1, uint32_t a2,
                                         uint32_t a3, uint32_t b0, uint32_t b1) {
    asm volatile(
        "mma.sync.aligned.m16n8k16.row.col.f32.bf16.bf16.f32 "
        "{%0,%1,%2,%3}, {%4,%5,%6,%7}, {%8,%9}, {%0,%1,%2,%3};"
        : "+f"(c0), "+f"(c1), "+f"(c2), "+f"(c3)
        : "r"(a0), "r"(a1), "r"(a2), "r"(a3), "r"(b0), "r"(b1));
}

// ---------------------------------------------------------------------------
// Grid-wide barrier (96 blocks, 1 CTA/SM -> all co-resident)
// ---------------------------------------------------------------------------
__device__ __forceinline__ void grid_barrier(unsigned &mygen) {
    __threadfence();
    __syncthreads();
    if (threadIdx.x == 0) {
        unsigned old = atomicAdd(&g_bar_count, 1u);
        if (old == GRU_NBLK - 1) {
            atomicExch(&g_bar_count, 0u);
            __threadfence();
            atomicAdd(&g_bar_gen, 1u);
        } else {
            while (*((volatile unsigned *)&g_bar_gen) == mygen) { }
        }
    }
    mygen += 1u;
    __syncthreads();
}

// ---------------------------------------------------------------------------
// int64-vs-int32 token dtype detection
// ---------------------------------------------------------------------------
__global__ void detect_kernel(const unsigned * __restrict__ xw) {
    if (threadIdx.x == 0 && blockIdx.x == 0) {
        int is64 = 1;
        for (int i = 1; i < 128; i += 2)
            if (xw[i] != 0u) { is64 = 0; break; }
        g_x_is64 = is64;
    }
}

// ---------------------------------------------------------------------------
// Tiled fp32 NT GEMM (unchanged; ~47 TF/s)
// ---------------------------------------------------------------------------
__global__ __launch_bounds__(256) void sgemm_nt(const float * __restrict__ A,
                                                const float * __restrict__ W,
                                                const float * __restrict__ bias,
                                                float * __restrict__ C,
                                                int M, int N, int K) {
    __shared__ float As[16][132];
    __shared__ float Ws[16][132];
    const int bm = blockIdx.y * 128;
    const int bn = blockIdx.x * 128;
    const int tid = threadIdx.x;
    const int tx = tid & 15;
    const int ty = tid >> 4;
    const int lr = tid >> 2;
    const int lc = (tid & 3) << 2;
    float acc[8][8];
#pragma unroll
    for (int i = 0; i < 8; ++i)
#pragma unroll
        for (int j = 0; j < 8; ++j) acc[i][j] = 0.f;
    const float *Ap = A + (size_t)(bm + lr) * K + lc;
    const float *Wp = W + (size_t)(bn + lr) * K + lc;
    const size_t half = (size_t)64 * K;
    for (int k0 = 0; k0 < K; k0 += 16) {
        float4 a0 = *(const float4 *)(Ap + k0);
        float4 a1 = *(const float4 *)(Ap + half + k0);
        float4 w0 = *(const float4 *)(Wp + k0);
        float4 w1 = *(const float4 *)(Wp + half + k0);
        __syncthreads();
        As[lc + 0][lr] = a0.x; As[lc + 1][lr] = a0.y; As[lc + 2][lr] = a0.z; As[lc + 3][lr] = a0.w;
        As[lc + 0][lr + 64] = a1.x; As[lc + 1][lr + 64] = a1.y; As[lc + 2][lr + 64] = a1.z; As[lc + 3][lr + 64] = a1.w;
        Ws[lc + 0][lr] = w0.x; Ws[lc + 1][lr] = w0.y; Ws[lc + 2][lr] = w0.z; Ws[lc + 3][lr] = w0.w;
        Ws[lc + 0][lr + 64] = w1.x; Ws[lc + 1][lr + 64] = w1.y; Ws[lc + 2][lr + 64] = w1.z; Ws[lc + 3][lr + 64] = w1.w;
        __syncthreads();
#pragma unroll
        for (int kk = 0; kk < 16; ++kk) {
            float af[8], wf[8];
            *(float4 *)&af[0] = *(const float4 *)&As[kk][ty * 4];
            *(float4 *)&af[4] = *(const float4 *)&As[kk][64 + ty * 4];
            *(float4 *)&wf[0] = *(const float4 *)&Ws[kk][tx * 4];
            *(float4 *)&wf[4] = *(const float4 *)&Ws[kk][64 + tx * 4];
#pragma unroll
            for (int i = 0; i < 8; ++i)
#pragma unroll
                for (int j = 0; j < 8; ++j) acc[i][j] += af[i] * wf[j];
        }
    }
    float bf[8];
#pragma unroll
    for (int j = 0; j < 8; ++j) {
        int col = bn + ((j < 4) ? (tx * 4 + j) : (64 + tx * 4 + j - 4));
        bf[j] = bias ? bias[col] : 0.f;
    }
#pragma unroll
    for (int i = 0; i < 8; ++i) {
        int row = bm + ((i < 4) ? (ty * 4 + i) : (64 + ty * 4 + i - 4));
        float4 v0, v1;
        v0.x = acc[i][0] + bf[0]; v0.y = acc[i][1] + bf[1];
        v0.z = acc[i][2] + bf[2]; v0.w = acc[i][3] + bf[3];
        v1.x = acc[i][4] + bf[4]; v1.y = acc[i][5] + bf[5];
        v1.z = acc[i][6] + bf[6]; v1.w = acc[i][7] + bf[7];
        *(float4 *)&C[(size_t)row * N + bn + tx * 4] = v0;
        *(float4 *)&C[(size_t)row * N + bn + 64 + tx * 4] = v1;
    }
}

// ---------------------------------------------------------------------------
// Persistent GRU scan on mma.sync tensor cores (split-bf16, 3 passes).
// CTA blk: mt = blk>>2 (128 gate-rows), kq = blk&3 (256-wide K quarter).
// Warp wid owns rows [mt*128 + wid*16, +16), K = full 256 quarter.
// Weight hi/lo fragments preloaded to registers (zero per-step traffic).
// ---------------------------------------------------------------------------
__global__ __launch_bounds__(GRU_THREADS, 1) void gru_mma(
        const float * __restrict__ Whh, const float * __restrict__ bhh,
        const float * __restrict__ xgv, const void * __restrict__ tokens,
        float * __restrict__ outp) {
    extern __shared__ char dynsm[];
    // 128B-align base
    uint32_t raw = smem_u32(dynsm);
    uint32_t base = (raw + 127u) & ~127u;
    char *wbuf = dynsm + (base - raw);
    const uint32_t sW   = base;
    const uint32_t sBhi = base;            // reused after prologue
    const uint32_t sBlo = base + 32 * ROW_B;
    char *bhi = wbuf;
    char *blo = wbuf + 32 * ROW_B;

    const int tid = threadIdx.x;
    const int wid = tid >> 5;
    const int lane = tid & 31;
    const int blk = blockIdx.x;
    const int mt = blk >> 2;
    const int kq = blk & 3;

    // ---- prologue: preload split-bf16 weight fragments into registers ----
    uint32_t aH[16][4], aL[16][4];
    const float *Wbase = Whh + (size_t)(mt * 128) * Dq + kq * 256;
    const uint32_t aAddr = sW + (uint32_t)(wid * 16 + (lane & 15)) * ROW_B
                         + (uint32_t)(lane >> 4) * 16;
#pragma unroll 1
    for (int pass = 0; pass < 2; ++pass) {
        for (int i = tid; i < 128 * 64; i += GRU_THREADS) {
            int row = i >> 6;
            int c4 = i & 63;
            float4 w = *(const float4 *)(Wbase + (size_t)row * Dq + c4 * 4);
            __nv_bfloat16 v0, v1, v2, v3;
            if (pass == 0) {
                v0 = __float2bfloat16(w.x); v1 = __float2bfloat16(w.y);
                v2 = __float2bfloat16(w.z); v3 = __float2bfloat16(w.w);
            } else {
                v0 = __float2bfloat16(w.x - __bfloat162float(__float2bfloat16(w.x)));
                v1 = __float2bfloat16(w.y - __bfloat162float(__float2bfloat16(w.y)));
                v2 = __float2bfloat16(w.z - __bfloat162float(__float2bfloat16(w.z)));
                v3 = __float2bfloat16(w.w - __bfloat162float(__float2bfloat16(w.w)));
            }
            char *dst = wbuf + row * ROW_B + c4 * 8;
            *(__nv_bfloat162 *)(dst)     = __nv_bfloat162(v0, v1);
            *(__nv_bfloat162 *)(dst + 4) = __nv_bfloat162(v2, v3);
        }
        __syncthreads();
        if (pass == 0) {
#pragma unroll
            for (int ks = 0; ks < 16; ++ks)
                ldmx4(aH[ks][0], aH[ks][1], aH[ks][2], aH[ks][3], aAddr + ks * 32);
        } else {
#pragma unroll
            for (int ks = 0; ks < 16; ++ks)
                ldmx4(aL[ks][0], aL[ks][1], aL[ks][2], aL[ks][3], aAddr + ks * 32);
        }
        __syncthreads();
    }

    // zero h state
    for (int i = blk * GRU_THREADS + tid; i < Bq * Dq; i += GRU_NBLK * GRU_THREADS) {
        g_h32[i] = 0.f;
        g_hhi[i] = __float2bfloat16(0.f);
        g_hlo[i] = __float2bfloat16(0.f);
    }

    unsigned mygen = *((volatile unsigned *)&g_bar_gen);
    grid_barrier(mygen);
    const int x64 = g_x_is64;

    // B ldmatrix lane address pieces: group g = lane>>3
    const int bRow = ((lane >> 4) & 1) * 8 + (lane & 7);   // (g>>1)*8 + lane%8
    const int bCol = ((lane >> 3) & 1) * 16;               // (g&1)*16 bytes

    for (int t = 0; t < Tq; ++t) {
        // ---- stage h quarter (bf16 hi/lo) into padded smem ----
        for (int i = tid; i < 32 * 32; i += GRU_THREADS) {
            int row = i >> 5;
            int c8 = i & 31;
            const size_t gsrc = (size_t)row * Dq + kq * 256 + c8 * 8;
            uint4 vh = __ldcg((const uint4 *)&g_hhi[gsrc]);
            uint4 vl = __ldcg((const uint4 *)&g_hlo[gsrc]);
            *(uint4 *)(bhi + row * ROW_B + c8 * 16) = vh;
            *(uint4 *)(blo + row * ROW_B + c8 * 16) = vl;
        }
        __syncthreads();

        // ---- 16x32x256 per warp: 3-pass split-bf16 HMMA ----
        float acc[4][4];
#pragma unroll
        for (int nt = 0; nt < 4; ++nt)
#pragma unroll
            for (int j = 0; j < 4; ++j) acc[nt][j] = 0.f;

#pragma unroll
        for (int ks = 0; ks < 16; ++ks) {
            uint32_t bh[8], bl[8];
#pragma unroll
            for (int pair = 0; pair < 2; ++pair) {
                uint32_t ba = (uint32_t)((pair * 16 + bRow) * ROW_B) + ks * 32 + bCol;
                ldmx4(bh[pair * 4 + 0], bh[pair * 4 + 1],
                      bh[pair * 4 + 2], bh[pair * 4 + 3], sBhi + ba);
                ldmx4(bl[pair * 4 + 0], bl[pair * 4 + 1],
                      bl[pair * 4 + 2], bl[pair * 4 + 3], sBlo + ba);
            }
#pragma unroll
            for (int nt = 0; nt < 4; ++nt) {
                const int ib = (nt >> 1) * 4 + (nt & 1) * 2;
                mma_bf16(acc[nt][0], acc[nt][1], acc[nt][2], acc[nt][3],
                         aH[ks][0], aH[ks][1], aH[ks][2], aH[ks][3],
                         bh[ib], bh[ib + 1]);
                mma_bf16(acc[nt][0], acc[nt][1], acc[nt][2], acc[nt][3],
                         aH[ks][0], aH[ks][1], aH[ks][2], aH[ks][3],
                         bl[ib], bl[ib + 1]);
                mma_bf16(acc[nt][0], acc[nt][1], acc[nt][2], acc[nt][3],
                         aL[ks][0], aL[ks][1], aL[ks][2], aL[ks][3],
                         bh[ib], bh[ib + 1]);
            }
        }

        // ---- epilogue: scatter 16x32 gate block to g_part ----
        {
            const int grow = mt * 128 + wid * 16 + (lane >> 2);
            const size_t rb0 = ((size_t)kq * G3 + grow) << 5;
            const size_t rb1 = ((size_t)kq * G3 + grow + 8) << 5;
#pragma unroll
            for (int nt = 0; nt < 4; ++nt) {
                const int b = nt * 8 + (lane & 3) * 2;
                float2 v0, v1;
                v0.x = acc[nt][0]; v0.y = acc[nt][1];
                v1.x = acc[nt][2]; v1.y = acc[nt][3];
                *(float2 *)&g_part[rb0 + b] = v0;
                *(float2 *)&g_part[rb1 + b] = v1;
            }
        }
        grid_barrier(mygen);

        // ---- activation: 64 CTAs x 512 elems (16 dims x 32 batches) ----
        if (blk < 64) {
#pragma unroll
            for (int e = 0; e < 2; ++e) {
                const int flat = tid * 2 + e;
                const int b = flat & 31;
                const int d = blk * 16 + (flat >> 5);
                float hr = 0.f, hz = 0.f, hn = 0.f;
#pragma unroll
                for (int q = 0; q < 4; ++q) {
                    hr += __ldcg(&g_part[(((size_t)q * G3 + d) << 5) + b]);
                    hz += __ldcg(&g_part[(((size_t)q * G3 + Dq + d) << 5) + b]);
                    hn += __ldcg(&g_part[(((size_t)q * G3 + 2 * Dq + d) << 5) + b]);
                }
                hr += __ldg(&bhh[d]);
                hz += __ldg(&bhh[Dq + d]);
                hn += __ldg(&bhh[2 * Dq + d]);
                size_t xb;
                if (tokens) {
                    int tok;
                    if (x64) tok = (int)(((const long long *)tokens)[b * Tq + t]);
                    else     tok = ((const int *)tokens)[b * Tq + t];
                    xb = (size_t)tok * G3 + d;
                } else {
                    xb = ((size_t)b * Tq + t) * G3 + d;
                }
                float xr = __ldg(&xgv[xb]);
                float xz = __ldg(&xgv[xb + Dq]);
                float xn = __ldg(&xgv[xb + 2 * Dq]);
                float hold = g_h32[b * Dq + d];
                float r = 1.f / (1.f + expf(-(xr + hr)));
                float z = 1.f / (1.f + expf(-(xz + hz)));
                float n = tanhf(xn + r * hn);
                float hnew = (1.f - z) * n + z * hold;
                g_h32[b * Dq + d] = hnew;
                __nv_bfloat16 hh = __float2bfloat16(hnew);
                g_hhi[b * Dq + d] = hh;
                g_hlo[b * Dq + d] = __float2bfloat16(hnew - __bfloat162float(hh));
                outp[((size_t)b * Tq + t) * Dq + d] = hnew;
            }
        }
        grid_barrier(mygen);
    }
}

// ---------------------------------------------------------------------------
// LayerNorm over last dim (1024), one block per row
// ---------------------------------------------------------------------------
__global__ __launch_bounds__(256) void ln_kernel(const float * __restrict__ in,
                                                 float * __restrict__ outp,
                                                 const float * __restrict__ gamma,
                                                 const float * __restrict__ beta) {
    __shared__ float red[2][8];
    const int row = blockIdx.x;
    const int tid = threadIdx.x;
    float4 x = *(const float4 *)&in[(size_t)row * Dq + tid * 4];
    float s = x.x + x.y + x.z + x.w;
    float q = x.x * x.x + x.y * x.y + x.z * x.z + x.w * x.w;
#pragma unroll
    for (int off = 16; off; off >>= 1) {
        s += __shfl_xor_sync(0xffffffffu, s, off);
        q += __shfl_xor_sync(0xffffffffu, q, off);
    }
    if ((tid & 31) == 0) { red[0][tid >> 5] = s; red[1][tid >> 5] = q; }
    __syncthreads();
    if (tid < 32) {
        float ss = (tid < 8) ? red[0][tid] : 0.f;
        float qq = (tid < 8) ? red[1][tid] : 0.f;
#pragma unroll
        for (int off = 4; off; off >>= 1) {
            ss += __shfl_xor_sync(0xffffffffu, ss, off);
            qq += __shfl_xor_sync(0xffffffffu, qq, off);
        }
        if (tid == 0) { red[0][0] = ss; red[1][0] = qq; }
    }
    __syncthreads();
    const float mean = red[0][0] * (1.f / Dq);
    const float var = red[1][0] * (1.f / Dq) - mean * mean;
    const float inv = rsqrtf(var + 1e-5f);
    float4 g  = *(const float4 *)&gamma[tid * 4];
    float4 be = *(const float4 *)&beta[tid * 4];
    float4 o;
    o.x = (x.x - mean) * inv * g.x + be.x;
    o.y = (x.y - mean) * inv * g.y + be.y;
    o.z = (x.z - mean) * inv * g.z + be.z;
    o.w = (x.w - mean) * inv * g.w + be.w;
    *(float4 *)&outp[(size_t)row * Dq + tid * 4] = o;
}

// ---------------------------------------------------------------------------
// Host driver. Inputs: x, E, Wih, Whh, bih, bhh, gamma, beta. Output f32.
// ---------------------------------------------------------------------------
extern "C" void kernel_launch(void *const *d_in, const int *in_sizes, int n_in,
                              void *d_out, int out_size) {
    (void)in_sizes; (void)n_in; (void)out_size;
    const void  *x     = d_in[0];
    const float *E     = (const float *)d_in[1];
    const float *Wih   = (const float *)d_in[2];
    const float *Whh   = (const float *)d_in[3];
    const float *bih   = (const float *)d_in[4];
    const float *bhh   = (const float *)d_in[5];
    const float *gamma = (const float *)d_in[6];
    const float *beta  = (const float *)d_in[7];
    float *out = (float *)d_out;

    float *act0 = nullptr, *act1 = nullptr, *xg = nullptr, *tab = nullptr;
    cudaGetSymbolAddress((void **)&act0, g_act0);
    cudaGetSymbolAddress((void **)&act1, g_act1);
    cudaGetSymbolAddress((void **)&xg, g_xg);
    cudaGetSymbolAddress((void **)&tab, g_tab);

    cudaFuncSetAttribute(gru_mma, cudaFuncAttributeMaxDynamicSharedMemorySize,
                         GRU_DYN_SMEM);

    detect_kernel<<<1, 32>>>((const unsigned *)x);

    // layer 0: per-vocab gate table + tensor-core scan
    {
        dim3 gt(G3 / 128, Vq / 128);
        sgemm_nt<<<gt, 256>>>(E, Wih, bih, tab, Vq, G3, Dq);
    }
    gru_mma<<<GRU_NBLK, GRU_THREADS, GRU_DYN_SMEM>>>(Whh, bhh, tab, x, act1);

    // layer 1: dense input-gate GEMM + tensor-core scan
    {
        dim3 gx(G3 / 128, Mq / 128);
        sgemm_nt<<<gx, 256>>>(act1, Wih + (size_t)G3 * Dq, bih + G3, xg, Mq, G3, Dq);
    }
    gru_mma<<<GRU_NBLK, GRU_THREADS, GRU_DYN_SMEM>>>(Whh + (size_t)G3 * Dq,
                                                     bhh + G3, xg, nullptr, act0);

    // LayerNorm + tied head
    ln_kernel<<<Mq, 256>>>(act0, act1, gamma, beta);
    dim3 gh(Vq / 128, Mq / 128);
    sgemm_nt<<<gh, 256>>>(act1, E, nullptr, out, Mq, Vq, Dq);
}

// round 7
// speedup vs baseline: 1.5023x; 1.2753x over previous
#include <cuda_runtime.h>
#include <cuda_bf16.h>
#include <cstdint>
#include <cstddef>

// ---------------------------------------------------------------------------
// Problem constants
// ---------------------------------------------------------------------------
#define Bq   32
#define Tq   512
#define Dq   1024
#define Vq   256
#define Mq   (Bq * Tq)      // 16384 rows
#define G3   (3 * Dq)       // 3072 gate rows

// ---------------------------------------------------------------------------
// Scratch (static device arrays; no allocation allowed)
// ---------------------------------------------------------------------------
__device__ float g_act0[(size_t)Mq * Dq];          // 64 MB
__device__ float g_act1[(size_t)Mq * Dq];          // 64 MB
__device__ float g_xg[(size_t)Mq * G3];            // 192 MB (layer-1 gates)
__device__ float g_tab[(size_t)Vq * G3];           // 3 MB  (layer-0 gate table)
__device__ __nv_bfloat16 g_hhi[2][Bq * Dq];        // bf16 hi of h (dbl-buffered)
__device__ __nv_bfloat16 g_hlo[2][Bq * Dq];        // bf16 lo of h
__device__ unsigned g_cnt8[8];                     // barrier arrival counters
__device__ unsigned g_gen2;                        // barrier generation
__device__ int g_x_is64;

// ---------------------------------------------------------------------------
// GRU config: 128 CTAs x (8 dims -> 24 gate rows pad 32) x full K=1024.
// Warp = (rowgroup rg in {0,1}, k-quarter kq in {0..3}).
// ---------------------------------------------------------------------------
#define GRU_NBLK    128
#define GRU_THREADS 256
#define ROWB        2064                 // 1024 bf16 + 8 pad = 2064 B row stride
#define SM_BLO_OFF  (32 * ROWB)          // 66048
#define SM_RED_OFF  (2 * 32 * ROWB)      // 132096
#define GRU_DYN_SMEM (SM_RED_OFF + 4 * 2 * 16 * 32 * 4 + 256)   // ~148.7 KB

__device__ __forceinline__ uint32_t smem_u32(const void *p) {
    uint32_t a;
    asm("{ .reg .u64 t; cvta.to.shared.u64 t, %1; cvt.u32.u64 %0, t; }"
        : "=r"(a) : "l"(p));
    return a;
}
__device__ __forceinline__ void ldmx4(uint32_t &r0, uint32_t &r1,
                                      uint32_t &r2, uint32_t &r3, uint32_t addr) {
    asm volatile("ldmatrix.sync.aligned.m8n8.x4.shared.b16 {%0,%1,%2,%3}, [%4];"
                 : "=r"(r0), "=r"(r1), "=r"(r2), "=r"(r3) : "r"(addr));
}
__device__ __forceinline__ void mma_bf16(float &c0, float &c1, float &c2, float &c3,
                                         uint32_t a0, uint32_t a1, uint32_t a2,
                                         uint32_t a3, uint32_t b0, uint32_t b1) {
    asm volatile(
        "mma.sync.aligned.m16n8k16.row.col.f32.bf16.bf16.f32 "
        "{%0,%1,%2,%3}, {%4,%5,%6,%7}, {%8,%9}, {%0,%1,%2,%3};"
        : "+f"(c0), "+f"(c1), "+f"(c2), "+f"(c3)
        : "r"(a0), "r"(a1), "r"(a2), "r"(a3), "r"(b0), "r"(b1));
}

// ---------------------------------------------------------------------------
// Grid barrier, single-crossing: 8-counter arrival tree + CTA0 release.
// Counters are monotonic across launches; `gen` is absolute (seeded from
// g_gen2 at kernel start, before any arrival -> race-free).
// ---------------------------------------------------------------------------
__device__ __forceinline__ void gbar(int blk, int tid, unsigned &gen) {
    gen += 1u;
    __threadfence();
    __syncthreads();
    if (blk == 0) {
        if (tid < 32) {
            if (tid == 0) atomicAdd(&g_cnt8[0], 1u);
            const unsigned tgt = gen * (GRU_NBLK / 8);
            for (;;) {
                unsigned v = (tid < 8) ? *(volatile unsigned *)&g_cnt8[tid] : tgt;
                if (__all_sync(0xffffffffu, v >= tgt)) break;
            }
            if (tid == 0) atomicExch(&g_gen2, gen);
        }
    } else if (tid == 0) {
        atomicAdd(&g_cnt8[blk & 7], 1u);
        while (*(volatile unsigned *)&g_gen2 < gen) { }
    }
    __threadfence();
    __syncthreads();
}

// ---------------------------------------------------------------------------
// int64-vs-int32 token dtype detection
// ---------------------------------------------------------------------------
__global__ void detect_kernel(const unsigned * __restrict__ xw) {
    if (threadIdx.x == 0 && blockIdx.x == 0) {
        int is64 = 1;
        for (int i = 1; i < 128; i += 2)
            if (xw[i] != 0u) { is64 = 0; break; }
        g_x_is64 = is64;
    }
}

// ---------------------------------------------------------------------------
// Tiled fp32 NT GEMM (unchanged; ~47 TF/s)
// ---------------------------------------------------------------------------
__global__ __launch_bounds__(256) void sgemm_nt(const float * __restrict__ A,
                                                const float * __restrict__ W,
                                                const float * __restrict__ bias,
                                                float * __restrict__ C,
                                                int M, int N, int K) {
    __shared__ float As[16][132];
    __shared__ float Ws[16][132];
    const int bm = blockIdx.y * 128;
    const int bn = blockIdx.x * 128;
    const int tid = threadIdx.x;
    const int tx = tid & 15;
    const int ty = tid >> 4;
    const int lr = tid >> 2;
    const int lc = (tid & 3) << 2;
    float acc[8][8];
#pragma unroll
    for (int i = 0; i < 8; ++i)
#pragma unroll
        for (int j = 0; j < 8; ++j) acc[i][j] = 0.f;
    const float *Ap = A + (size_t)(bm + lr) * K + lc;
    const float *Wp = W + (size_t)(bn + lr) * K + lc;
    const size_t half = (size_t)64 * K;
    for (int k0 = 0; k0 < K; k0 += 16) {
        float4 a0 = *(const float4 *)(Ap + k0);
        float4 a1 = *(const float4 *)(Ap + half + k0);
        float4 w0 = *(const float4 *)(Wp + k0);
        float4 w1 = *(const float4 *)(Wp + half + k0);
        __syncthreads();
        As[lc + 0][lr] = a0.x; As[lc + 1][lr] = a0.y; As[lc + 2][lr] = a0.z; As[lc + 3][lr] = a0.w;
        As[lc + 0][lr + 64] = a1.x; As[lc + 1][lr + 64] = a1.y; As[lc + 2][lr + 64] = a1.z; As[lc + 3][lr + 64] = a1.w;
        Ws[lc + 0][lr] = w0.x; Ws[lc + 1][lr] = w0.y; Ws[lc + 2][lr] = w0.z; Ws[lc + 3][lr] = w0.w;
        Ws[lc + 0][lr + 64] = w1.x; Ws[lc + 1][lr + 64] = w1.y; Ws[lc + 2][lr + 64] = w1.z; Ws[lc + 3][lr + 64] = w1.w;
        __syncthreads();
#pragma unroll
        for (int kk = 0; kk < 16; ++kk) {
            float af[8], wf[8];
            *(float4 *)&af[0] = *(const float4 *)&As[kk][ty * 4];
            *(float4 *)&af[4] = *(const float4 *)&As[kk][64 + ty * 4];
            *(float4 *)&wf[0] = *(const float4 *)&Ws[kk][tx * 4];
            *(float4 *)&wf[4] = *(const float4 *)&Ws[kk][64 + tx * 4];
#pragma unroll
            for (int i = 0; i < 8; ++i)
#pragma unroll
                for (int j = 0; j < 8; ++j) acc[i][j] += af[i] * wf[j];
        }
    }
    float bf[8];
#pragma unroll
    for (int j = 0; j < 8; ++j) {
        int col = bn + ((j < 4) ? (tx * 4 + j) : (64 + tx * 4 + j - 4));
        bf[j] = bias ? bias[col] : 0.f;
    }
#pragma unroll
    for (int i = 0; i < 8; ++i) {
        int row = bm + ((i < 4) ? (ty * 4 + i) : (64 + ty * 4 + i - 4));
        float4 v0, v1;
        v0.x = acc[i][0] + bf[0]; v0.y = acc[i][1] + bf[1];
        v0.z = acc[i][2] + bf[2]; v0.w = acc[i][3] + bf[3];
        v1.x = acc[i][4] + bf[4]; v1.y = acc[i][5] + bf[5];
        v1.z = acc[i][6] + bf[6]; v1.w = acc[i][7] + bf[7];
        *(float4 *)&C[(size_t)row * N + bn + tx * 4] = v0;
        *(float4 *)&C[(size_t)row * N + bn + 64 + tx * 4] = v1;
    }
}

// ---------------------------------------------------------------------------
// Persistent GRU scan, one grid barrier per step.
// CTA blk owns dims d0 = blk*8 .. +8 (rows r/z/n = g*8+dd, 24 rows pad 32).
// Warp (rg, kq): rows rg*16..+16, K quarter kq*256..+256. Full K in-CTA,
// k-reduction via smem, fused activation, h state register-resident.
// ---------------------------------------------------------------------------
__global__ __launch_bounds__(GRU_THREADS, 1) void gru_mma(
        const float * __restrict__ Whh, const float * __restrict__ bhh,
        const float * __restrict__ xgv, const void * __restrict__ tokens,
        float * __restrict__ outp) {
    extern __shared__ char dynsm[];
    uint32_t raw = smem_u32(dynsm);
    uint32_t base = (raw + 127u) & ~127u;
    char *pb = dynsm + (base - raw);
    char *sB_hi = pb;
    char *sB_lo = pb + SM_BLO_OFF;
    float *red = (float *)(pb + SM_RED_OFF);       // [kq*2+rg][16][32]
    const uint32_t sBhiA = base, sBloA = base + SM_BLO_OFF;

    const int tid  = threadIdx.x;
    const int wid  = tid >> 5;
    const int lane = tid & 31;
    const int blk  = blockIdx.x;
    const int d0   = blk * 8;
    const int rg   = wid & 1;
    const int kq   = wid >> 1;

    // ---- prologue: split-bf16 weight fragments into registers ----
    uint32_t aH[16][4], aL[16][4];
    const uint32_t aAddr = sBhiA + (uint32_t)(rg * 16 + (lane & 15)) * ROWB
                         + (uint32_t)(lane >> 4) * 16 + (uint32_t)kq * 512;
#pragma unroll 1
    for (int pass = 0; pass < 2; ++pass) {
        for (int i = tid; i < 32 * 128; i += GRU_THREADS) {
            int row = i >> 7;          // 0..31
            int c = i & 127;           // 16B group (8 bf16)
            union { __nv_bfloat16 h[8]; uint4 u; } v;
            if (row < 24) {
                int g = row >> 3, dd = row & 7;
                const float *src = Whh + (size_t)(g * Dq + d0 + dd) * Dq + c * 8;
                float4 w0 = *(const float4 *)src;
                float4 w1 = *(const float4 *)(src + 4);
                float f[8] = {w0.x, w0.y, w0.z, w0.w, w1.x, w1.y, w1.z, w1.w};
#pragma unroll
                for (int j = 0; j < 8; ++j) {
                    __nv_bfloat16 hi = __float2bfloat16(f[j]);
                    v.h[j] = (pass == 0) ? hi
                           : __float2bfloat16(f[j] - __bfloat162float(hi));
                }
            } else {
                v.u = make_uint4(0u, 0u, 0u, 0u);
            }
            *(uint4 *)(sB_hi + row * ROWB + c * 16) = v.u;
        }
        __syncthreads();
        if (pass == 0) {
#pragma unroll
            for (int ks = 0; ks < 16; ++ks)
                ldmx4(aH[ks][0], aH[ks][1], aH[ks][2], aH[ks][3], aAddr + ks * 32);
        } else {
#pragma unroll
            for (int ks = 0; ks < 16; ++ks)
                ldmx4(aL[ks][0], aL[ks][1], aL[ks][2], aL[ks][3], aAddr + ks * 32);
        }
        __syncthreads();
    }

    // zero both h buffers
    for (int i = blk * GRU_THREADS + tid; i < 2 * Bq * Dq;
         i += GRU_NBLK * GRU_THREADS) {
        ((__nv_bfloat16 *)g_hhi)[i] = __float2bfloat16(0.f);
        ((__nv_bfloat16 *)g_hlo)[i] = __float2bfloat16(0.f);
    }

    unsigned gen = *(volatile unsigned *)&g_gen2;   // quiescent base (race-free)
    gbar(blk, tid, gen);
    const int x64 = g_x_is64;

    // activation constants (thread -> (dd = tid>>5, b = tid&31))
    const int ab = tid & 31;
    const int ad = tid >> 5;
    const int dglob = d0 + ad;
    const float bh_r = __ldg(bhh + dglob);
    const float bh_z = __ldg(bhh + Dq + dglob);
    const float bh_n = __ldg(bhh + 2 * Dq + dglob);
    float hold = 0.f;

    // B ldmatrix lane pieces
    const int bRow = ((lane >> 4) & 1) * 8 + (lane & 7);
    const int bCol = ((lane >> 3) & 1) * 16;
    const uint32_t bBase = (uint32_t)kq * 512 + (uint32_t)bCol;

    for (int t = 0; t < Tq; ++t) {
        const __nv_bfloat16 *hinH = g_hhi[t & 1];
        const __nv_bfloat16 *hinL = g_hlo[t & 1];
        __nv_bfloat16 *houtH = g_hhi[(t + 1) & 1];
        __nv_bfloat16 *houtL = g_hlo[(t + 1) & 1];

        // prefetch input gates early (hidden under staging + MMA)
        float xr, xz, xn;
        {
            size_t xb;
            if (tokens) {
                int tok;
                if (x64) tok = (int)(((const long long *)tokens)[ab * Tq + t]);
                else     tok = ((const int *)tokens)[ab * Tq + t];
                xb = (size_t)tok * G3 + dglob;
            } else {
                xb = ((size_t)ab * Tq + t) * G3 + dglob;
            }
            xr = __ldg(xgv + xb);
            xz = __ldg(xgv + xb + Dq);
            xn = __ldg(xgv + xb + 2 * Dq);
        }

        // ---- stage full h (bf16 hi/lo) into smem ----
#pragma unroll
        for (int j = 0; j < 16; ++j) {
            int idx = tid + j * GRU_THREADS;     // 0..4095
            int row = idx >> 7;
            int c = idx & 127;
            uint4 vh = __ldcg((const uint4 *)(hinH + row * Dq + c * 8));
            uint4 vl = __ldcg((const uint4 *)(hinL + row * Dq + c * 8));
            *(uint4 *)(sB_hi + row * ROWB + c * 16) = vh;
            *(uint4 *)(sB_lo + row * ROWB + c * 16) = vl;
        }
        __syncthreads();

        // ---- per-warp 32x32x256 split-bf16 HMMA (3 passes) ----
        float acc[4][4];
#pragma unroll
        for (int nt = 0; nt < 4; ++nt)
#pragma unroll
            for (int j = 0; j < 4; ++j) acc[nt][j] = 0.f;

#pragma unroll
        for (int ks = 0; ks < 16; ++ks) {
            uint32_t bh[8], bl[8];
#pragma unroll
            for (int pair = 0; pair < 2; ++pair) {
                uint32_t ba = (uint32_t)((pair * 16 + bRow) * ROWB) + bBase + ks * 32;
                ldmx4(bh[pair * 4 + 0], bh[pair * 4 + 1],
                      bh[pair * 4 + 2], bh[pair * 4 + 3], sBhiA + ba);
                ldmx4(bl[pair * 4 + 0], bl[pair * 4 + 1],
                      bl[pair * 4 + 2], bl[pair * 4 + 3], sBloA + ba);
            }
#pragma unroll
            for (int nt = 0; nt < 4; ++nt) {
                const int ib = nt * 2;
                mma_bf16(acc[nt][0], acc[nt][1], acc[nt][2], acc[nt][3],
                         aH[ks][0], aH[ks][1], aH[ks][2], aH[ks][3],
                         bh[ib], bh[ib + 1]);
                mma_bf16(acc[nt][0], acc[nt][1], acc[nt][2], acc[nt][3],
                         aH[ks][0], aH[ks][1], aH[ks][2], aH[ks][3],
                         bl[ib], bl[ib + 1]);
                mma_bf16(acc[nt][0], acc[nt][1], acc[nt][2], acc[nt][3],
                         aL[ks][0], aL[ks][1], aL[ks][2], aL[ks][3],
                         bh[ib], bh[ib + 1]);
            }
        }

        // ---- intra-CTA k-reduction staging ----
        {
            float *rb = red + (size_t)((kq * 2 + rg) * 16 + (lane >> 2)) * 32;
#pragma unroll
            for (int nt = 0; nt < 4; ++nt) {
                const int b = nt * 8 + (lane & 3) * 2;
                float2 v0, v1;
                v0.x = acc[nt][0]; v0.y = acc[nt][1];
                v1.x = acc[nt][2]; v1.y = acc[nt][3];
                *(float2 *)(rb + b) = v0;
                *(float2 *)(rb + 8 * 32 + b) = v1;
            }
        }
        __syncthreads();

        // ---- fused activation (one elem per thread) ----
        {
            float hr = 0.f, hz = 0.f, hn = 0.f;
#pragma unroll
            for (int q = 0; q < 4; ++q) {
                hr += red[((q * 2 + 0) * 16 + ad) * 32 + ab];
                hz += red[((q * 2 + 0) * 16 + 8 + ad) * 32 + ab];
                hn += red[((q * 2 + 1) * 16 + ad) * 32 + ab];
            }
            hr += bh_r; hz += bh_z; hn += bh_n;
            float r = 1.f / (1.f + expf(-(xr + hr)));
            float z = 1.f / (1.f + expf(-(xz + hz)));
            float n = tanhf(xn + r * hn);
            float hnew = (1.f - z) * n + z * hold;
            hold = hnew;
            __nv_bfloat16 hh = __float2bfloat16(hnew);
            houtH[ab * Dq + dglob] = hh;
            houtL[ab * Dq + dglob] = __float2bfloat16(hnew - __bfloat162float(hh));
            outp[((size_t)ab * Tq + t) * Dq + dglob] = hnew;
        }
        gbar(blk, tid, gen);
    }
}

// ---------------------------------------------------------------------------
// LayerNorm over last dim (1024), one block per row
// ---------------------------------------------------------------------------
__global__ __launch_bounds__(256) void ln_kernel(const float * __restrict__ in,
                                                 float * __restrict__ outp,
                                                 const float * __restrict__ gamma,
                                                 const float * __restrict__ beta) {
    __shared__ float red[2][8];
    const int row = blockIdx.x;
    const int tid = threadIdx.x;
    float4 x = *(const float4 *)&in[(size_t)row * Dq + tid * 4];
    float s = x.x + x.y + x.z + x.w;
    float q = x.x * x.x + x.y * x.y + x.z * x.z + x.w * x.w;
#pragma unroll
    for (int off = 16; off; off >>= 1) {
        s += __shfl_xor_sync(0xffffffffu, s, off);
        q += __shfl_xor_sync(0xffffffffu, q, off);
    }
    if ((tid & 31) == 0) { red[0][tid >> 5] = s; red[1][tid >> 5] = q; }
    __syncthreads();
    if (tid < 32) {
        float ss = (tid < 8) ? red[0][tid] : 0.f;
        float qq = (tid < 8) ? red[1][tid] : 0.f;
#pragma unroll
        for (int off = 4; off; off >>= 1) {
            ss += __shfl_xor_sync(0xffffffffu, ss, off);
            qq += __shfl_xor_sync(0xffffffffu, qq, off);
        }
        if (tid == 0) { red[0][0] = ss; red[1][0] = qq; }
    }
    __syncthreads();
    const float mean = red[0][0] * (1.f / Dq);
    const float var = red[1][0] * (1.f / Dq) - mean * mean;
    const float inv = rsqrtf(var + 1e-5f);
    float4 g  = *(const float4 *)&gamma[tid * 4];
    float4 be = *(const float4 *)&beta[tid * 4];
    float4 o;
    o.x = (x.x - mean) * inv * g.x + be.x;
    o.y = (x.y - mean) * inv * g.y + be.y;
    o.z = (x.z - mean) * inv * g.z + be.z;
    o.w = (x.w - mean) * inv * g.w + be.w;
    *(float4 *)&outp[(size_t)row * Dq + tid * 4] = o;
}

// ---------------------------------------------------------------------------
// Host driver. Inputs: x, E, Wih, Whh, bih, bhh, gamma, beta. Output f32.
// ---------------------------------------------------------------------------
extern "C" void kernel_launch(void *const *d_in, const int *in_sizes, int n_in,
                              void *d_out, int out_size) {
    (void)in_sizes; (void)n_in; (void)out_size;
    const void  *x     = d_in[0];
    const float *E     = (const float *)d_in[1];
    const float *Wih   = (const float *)d_in[2];
    const float *Whh   = (const float *)d_in[3];
    const float *bih   = (const float *)d_in[4];
    const float *bhh   = (const float *)d_in[5];
    const float *gamma = (const float *)d_in[6];
    const float *beta  = (const float *)d_in[7];
    float *out = (float *)d_out;

    float *act0 = nullptr, *act1 = nullptr, *xg = nullptr, *tab = nullptr;
    cudaGetSymbolAddress((void **)&act0, g_act0);
    cudaGetSymbolAddress((void **)&act1, g_act1);
    cudaGetSymbolAddress((void **)&xg, g_xg);
    cudaGetSymbolAddress((void **)&tab, g_tab);

    cudaFuncSetAttribute(gru_mma, cudaFuncAttributeMaxDynamicSharedMemorySize,
                         GRU_DYN_SMEM);

    detect_kernel<<<1, 32>>>((const unsigned *)x);

    // layer 0: per-vocab gate table + tensor-core scan
    {
        dim3 gt(G3 / 128, Vq / 128);
        sgemm_nt<<<gt, 256>>>(E, Wih, bih, tab, Vq, G3, Dq);
    }
    gru_mma<<<GRU_NBLK, GRU_THREADS, GRU_DYN_SMEM>>>(Whh, bhh, tab, x, act1);

    // layer 1: dense input-gate GEMM + tensor-core scan
    {
        dim3 gx(G3 / 128, Mq / 128);
        sgemm_nt<<<gx, 256>>>(act1, Wih + (size_t)G3 * Dq, bih + G3, xg, Mq, G3, Dq);
    }
    gru_mma<<<GRU_NBLK, GRU_THREADS, GRU_DYN_SMEM>>>(Whh + (size_t)G3 * Dq,
                                                     bhh + G3, xg, nullptr, act0);

    // LayerNorm + tied head
    ln_kernel<<<Mq, 256>>>(act0, act1, gamma, beta);
    dim3 gh(Vq / 128, Mq / 128);
    sgemm_nt<<<gh, 256>>>(act1, E, nullptr, out, Mq, Vq, Dq);
}

// round 8
// speedup vs baseline: 1.7219x; 1.1461x over previous
#include <cuda_runtime.h>
#include <cuda_bf16.h>
#include <cstdint>
#include <cstddef>

// ---------------------------------------------------------------------------
// Problem constants
// ---------------------------------------------------------------------------
#define Bq   32
#define Tq   512
#define Dq   1024
#define Vq   256
#define Mq   (Bq * Tq)      // 16384 rows
#define G3   (3 * Dq)       // 3072 gate rows

// ---------------------------------------------------------------------------
// Scratch (static device arrays; no allocation allowed)
// ---------------------------------------------------------------------------
__device__ float g_act0[(size_t)Mq * Dq];          // 64 MB
__device__ float g_act1[(size_t)Mq * Dq];          // 64 MB
__device__ float g_xg[(size_t)Mq * G3];            // 192 MB (layer-1 gates)
__device__ float g_tab[(size_t)Vq * G3];           // 3 MB  (layer-0 gate table)
__device__ __nv_bfloat16 g_hhi[2][Bq * Dq];        // bf16 hi of h (dbl-buffered)
__device__ __nv_bfloat16 g_hlo[2][Bq * Dq];        // bf16 lo of h
__device__ unsigned g_cnt8[8];                     // barrier arrival counters
__device__ unsigned g_gen2;                        // barrier generation
__device__ int g_x_is64;

// ---------------------------------------------------------------------------
// GRU config: 128 CTAs x (8 dims -> 24 gate rows pad 32) x full K=1024.
// ---------------------------------------------------------------------------
#define GRU_NBLK    128
#define GRU_THREADS 256
#define ROWB        2064                 // 1024 bf16 + 8 pad = 2064 B row stride
#define SM_BLO_OFF  (32 * ROWB)          // 66048
#define SM_RED_OFF  (2 * 32 * ROWB)      // 132096
#define GRU_DYN_SMEM (SM_RED_OFF + 4 * 2 * 16 * 32 * 4 + 256)   // ~148.7 KB

// ---------------------------------------------------------------------------
// bf16 HMMA GEMM config (3-pass split): BM=128, BN=64, BK=64, 256 thr
// ---------------------------------------------------------------------------
#define GM_STRIDE  144                   // 64 bf16 = 128 B + 16 pad
#define GM_A_BYTES (128 * GM_STRIDE)     // 18432
#define GM_W_BYTES (64 * GM_STRIDE)      // 9216
#define GM_SMEM    (2 * GM_A_BYTES + 2 * GM_W_BYTES)   // 55296

__device__ __forceinline__ uint32_t smem_u32(const void *p) {
    uint32_t a;
    asm("{ .reg .u64 t; cvta.to.shared.u64 t, %1; cvt.u32.u64 %0, t; }"
        : "=r"(a) : "l"(p));
    return a;
}
__device__ __forceinline__ void ldmx4(uint32_t &r0, uint32_t &r1,
                                      uint32_t &r2, uint32_t &r3, uint32_t addr) {
    asm volatile("ldmatrix.sync.aligned.m8n8.x4.shared.b16 {%0,%1,%2,%3}, [%4];"
                 : "=r"(r0), "=r"(r1), "=r"(r2), "=r"(r3) : "r"(addr));
}
__device__ __forceinline__ void mma_bf16(float &c0, float &c1, float &c2, float &c3,
                                         uint32_t a0, uint32_t a1, uint32_t a2,
                                         uint32_t a3, uint32_t b0, uint32_t b1) {
    asm volatile(
        "mma.sync.aligned.m16n8k16.row.col.f32.bf16.bf16.f32 "
        "{%0,%1,%2,%3}, {%4,%5,%6,%7}, {%8,%9}, {%0,%1,%2,%3};"
        : "+f"(c0), "+f"(c1), "+f"(c2), "+f"(c3)
        : "r"(a0), "r"(a1), "r"(a2), "r"(a3), "r"(b0), "r"(b1));
}
__device__ __forceinline__ void split4(float4 v, uint2 &hi, uint2 &lo) {
    __nv_bfloat16 h0 = __float2bfloat16(v.x);
    __nv_bfloat16 h1 = __float2bfloat16(v.y);
    __nv_bfloat16 h2 = __float2bfloat16(v.z);
    __nv_bfloat16 h3 = __float2bfloat16(v.w);
    union { __nv_bfloat162 b[2]; uint2 u; } H, L;
    H.b[0] = __nv_bfloat162(h0, h1);
    H.b[1] = __nv_bfloat162(h2, h3);
    L.b[0] = __nv_bfloat162(__float2bfloat16(v.x - __bfloat162float(h0)),
                            __float2bfloat16(v.y - __bfloat162float(h1)));
    L.b[1] = __nv_bfloat162(__float2bfloat16(v.z - __bfloat162float(h2)),
                            __float2bfloat16(v.w - __bfloat162float(h3)));
    hi = H.u; lo = L.u;
}

// ---------------------------------------------------------------------------
// Grid barrier, single-crossing: 8-counter arrival tree + CTA0 release.
// ---------------------------------------------------------------------------
__device__ __forceinline__ void gbar(int blk, int tid, unsigned &gen) {
    gen += 1u;
    __threadfence();
    __syncthreads();
    if (blk == 0) {
        if (tid < 32) {
            if (tid == 0) atomicAdd(&g_cnt8[0], 1u);
            const unsigned tgt = gen * (GRU_NBLK / 8);
            for (;;) {
                unsigned v = (tid < 8) ? *(volatile unsigned *)&g_cnt8[tid] : tgt;
                if (__all_sync(0xffffffffu, v >= tgt)) break;
            }
            if (tid == 0) atomicExch(&g_gen2, gen);
        }
    } else if (tid == 0) {
        atomicAdd(&g_cnt8[blk & 7], 1u);
        while (*(volatile unsigned *)&g_gen2 < gen) { }
    }
    __threadfence();
    __syncthreads();
}

// ---------------------------------------------------------------------------
// int64-vs-int32 token dtype detection
// ---------------------------------------------------------------------------
__global__ void detect_kernel(const unsigned * __restrict__ xw) {
    if (threadIdx.x == 0 && blockIdx.x == 0) {
        int is64 = 1;
        for (int i = 1; i < 128; i += 2)
            if (xw[i] != 0u) { is64 = 0; break; }
        g_x_is64 = is64;
    }
}

// ---------------------------------------------------------------------------
// Split-bf16 (3-pass) HMMA NT GEMM: C[M,N] = A[M,K]*W[N,K]^T (+bias).
// fp32 operands split to bf16 hi/lo on load. M%128==0, N%64==0, K%64==0.
// Fragment maps identical to the verified gru_mma kernel.
// ---------------------------------------------------------------------------
__global__ __launch_bounds__(256) void gemm_bf3(const float * __restrict__ A,
                                                const float * __restrict__ W,
                                                const float * __restrict__ bias,
                                                float * __restrict__ C,
                                                int M, int N, int K) {
    extern __shared__ char sm[];
    char *sAhi = sm;
    char *sAlo = sm + GM_A_BYTES;
    char *sWhi = sm + 2 * GM_A_BYTES;
    char *sWlo = sWhi + GM_W_BYTES;
    const uint32_t aHiA = smem_u32(sAhi);
    const uint32_t aLoA = smem_u32(sAlo);
    const uint32_t wHiA = smem_u32(sWhi);
    const uint32_t wLoA = smem_u32(sWlo);

    const int tid = threadIdx.x;
    const int lane = tid & 31;
    const int wid = tid >> 5;
    const int wm = wid & 3;            // warp M index (0..3) -> rows wm*32
    const int wn = wid >> 2;           // warp N index (0..1) -> cols wn*32
    const int bm = blockIdx.y * 128;
    const int bn = blockIdx.x * 64;

    float acc[2][4][4];
#pragma unroll
    for (int rg = 0; rg < 2; ++rg)
#pragma unroll
        for (int nt = 0; nt < 4; ++nt)
#pragma unroll
            for (int j = 0; j < 4; ++j) acc[rg][nt][j] = 0.f;

    const uint32_t aAddr = aHiA + (uint32_t)(wm * 32 + (lane & 15)) * GM_STRIDE
                         + (uint32_t)(lane >> 4) * 16;
    const uint32_t aLoOff = aLoA - aHiA;
    const int bRow = ((lane >> 4) & 1) * 8 + (lane & 7);
    const int bCol = ((lane >> 3) & 1) * 16;

    for (int k0 = 0; k0 < K; k0 += 64) {
        float4 av[8], wv[4];
#pragma unroll
        for (int j = 0; j < 8; ++j) {
            int idx = tid + j * 256, r = idx >> 4, c = idx & 15;
            av[j] = *(const float4 *)(A + (size_t)(bm + r) * K + k0 + c * 4);
        }
#pragma unroll
        for (int j = 0; j < 4; ++j) {
            int idx = tid + j * 256, r = idx >> 4, c = idx & 15;
            wv[j] = *(const float4 *)(W + (size_t)(bn + r) * K + k0 + c * 4);
        }
        __syncthreads();
#pragma unroll
        for (int j = 0; j < 8; ++j) {
            int idx = tid + j * 256, r = idx >> 4, c = idx & 15;
            uint2 hi, lo;
            split4(av[j], hi, lo);
            *(uint2 *)(sAhi + r * GM_STRIDE + c * 8) = hi;
            *(uint2 *)(sAlo + r * GM_STRIDE + c * 8) = lo;
        }
#pragma unroll
        for (int j = 0; j < 4; ++j) {
            int idx = tid + j * 256, r = idx >> 4, c = idx & 15;
            uint2 hi, lo;
            split4(wv[j], hi, lo);
            *(uint2 *)(sWhi + r * GM_STRIDE + c * 8) = hi;
            *(uint2 *)(sWlo + r * GM_STRIDE + c * 8) = lo;
        }
        __syncthreads();

        uint32_t aH[2][4][4], aL[2][4][4];
#pragma unroll
        for (int rg = 0; rg < 2; ++rg)
#pragma unroll
            for (int ks = 0; ks < 4; ++ks) {
                uint32_t ad = aAddr + (uint32_t)(rg * 16 * GM_STRIDE) + ks * 32;
                ldmx4(aH[rg][ks][0], aH[rg][ks][1], aH[rg][ks][2], aH[rg][ks][3], ad);
                ldmx4(aL[rg][ks][0], aL[rg][ks][1], aL[rg][ks][2], aL[rg][ks][3],
                      ad + aLoOff);
            }
#pragma unroll
        for (int ks = 0; ks < 4; ++ks) {
            uint32_t bh[8], bl[8];
#pragma unroll
            for (int pair = 0; pair < 2; ++pair) {
                uint32_t ba = (uint32_t)((wn * 32 + pair * 16 + bRow) * GM_STRIDE)
                            + bCol + ks * 32;
                ldmx4(bh[pair * 4 + 0], bh[pair * 4 + 1],
                      bh[pair * 4 + 2], bh[pair * 4 + 3], wHiA + ba);
                ldmx4(bl[pair * 4 + 0], bl[pair * 4 + 1],
                      bl[pair * 4 + 2], bl[pair * 4 + 3], wLoA + ba);
            }
#pragma unroll
            for (int rg = 0; rg < 2; ++rg)
#pragma unroll
                for (int nt = 0; nt < 4; ++nt) {
                    const int ib = nt * 2;
                    mma_bf16(acc[rg][nt][0], acc[rg][nt][1], acc[rg][nt][2], acc[rg][nt][3],
                             aH[rg][ks][0], aH[rg][ks][1], aH[rg][ks][2], aH[rg][ks][3],
                             bh[ib], bh[ib + 1]);
                    mma_bf16(acc[rg][nt][0], acc[rg][nt][1], acc[rg][nt][2], acc[rg][nt][3],
                             aH[rg][ks][0], aH[rg][ks][1], aH[rg][ks][2], aH[rg][ks][3],
                             bl[ib], bl[ib + 1]);
                    mma_bf16(acc[rg][nt][0], acc[rg][nt][1], acc[rg][nt][2], acc[rg][nt][3],
                             aL[rg][ks][0], aL[rg][ks][1], aL[rg][ks][2], aL[rg][ks][3],
                             bh[ib], bh[ib + 1]);
                }
        }
    }

    // epilogue: bias + direct global store (32B-sector aligned float2s)
    float b2x[4], b2y[4];
#pragma unroll
    for (int nt = 0; nt < 4; ++nt) {
        int col = bn + wn * 32 + nt * 8 + (lane & 3) * 2;
        b2x[nt] = bias ? __ldg(bias + col) : 0.f;
        b2y[nt] = bias ? __ldg(bias + col + 1) : 0.f;
    }
#pragma unroll
    for (int rg = 0; rg < 2; ++rg)
#pragma unroll
        for (int nt = 0; nt < 4; ++nt) {
            int row = bm + wm * 32 + rg * 16 + (lane >> 2);
            int col = bn + wn * 32 + nt * 8 + (lane & 3) * 2;
            float2 v0, v1;
            v0.x = acc[rg][nt][0] + b2x[nt];
            v0.y = acc[rg][nt][1] + b2y[nt];
            v1.x = acc[rg][nt][2] + b2x[nt];
            v1.y = acc[rg][nt][3] + b2y[nt];
            *(float2 *)(C + (size_t)row * N + col) = v0;
            *(float2 *)(C + (size_t)(row + 8) * N + col) = v1;
        }
}

// ---------------------------------------------------------------------------
// Persistent GRU scan, one grid barrier per step (unchanged from R7 pass).
// ---------------------------------------------------------------------------
__global__ __launch_bounds__(GRU_THREADS, 1) void gru_mma(
        const float * __restrict__ Whh, const float * __restrict__ bhh,
        const float * __restrict__ xgv, const void * __restrict__ tokens,
        float * __restrict__ outp) {
    extern __shared__ char dynsm[];
    uint32_t raw = smem_u32(dynsm);
    uint32_t base = (raw + 127u) & ~127u;
    char *pb = dynsm + (base - raw);
    char *sB_hi = pb;
    char *sB_lo = pb + SM_BLO_OFF;
    float *red = (float *)(pb + SM_RED_OFF);       // [kq*2+rg][16][32]
    const uint32_t sBhiA = base, sBloA = base + SM_BLO_OFF;

    const int tid  = threadIdx.x;
    const int wid  = tid >> 5;
    const int lane = tid & 31;
    const int blk  = blockIdx.x;
    const int d0   = blk * 8;
    const int rg   = wid & 1;
    const int kq   = wid >> 1;

    // ---- prologue: split-bf16 weight fragments into registers ----
    uint32_t aH[16][4], aL[16][4];
    const uint32_t aAddr = sBhiA + (uint32_t)(rg * 16 + (lane & 15)) * ROWB
                         + (uint32_t)(lane >> 4) * 16 + (uint32_t)kq * 512;
#pragma unroll 1
    for (int pass = 0; pass < 2; ++pass) {
        for (int i = tid; i < 32 * 128; i += GRU_THREADS) {
            int row = i >> 7;          // 0..31
            int c = i & 127;           // 16B group (8 bf16)
            union { __nv_bfloat16 h[8]; uint4 u; } v;
            if (row < 24) {
                int g = row >> 3, dd = row & 7;
                const float *src = Whh + (size_t)(g * Dq + d0 + dd) * Dq + c * 8;
                float4 w0 = *(const float4 *)src;
                float4 w1 = *(const float4 *)(src + 4);
                float f[8] = {w0.x, w0.y, w0.z, w0.w, w1.x, w1.y, w1.z, w1.w};
#pragma unroll
                for (int j = 0; j < 8; ++j) {
                    __nv_bfloat16 hi = __float2bfloat16(f[j]);
                    v.h[j] = (pass == 0) ? hi
                           : __float2bfloat16(f[j] - __bfloat162float(hi));
                }
            } else {
                v.u = make_uint4(0u, 0u, 0u, 0u);
            }
            *(uint4 *)(sB_hi + row * ROWB + c * 16) = v.u;
        }
        __syncthreads();
        if (pass == 0) {
#pragma unroll
            for (int ks = 0; ks < 16; ++ks)
                ldmx4(aH[ks][0], aH[ks][1], aH[ks][2], aH[ks][3], aAddr + ks * 32);
        } else {
#pragma unroll
            for (int ks = 0; ks < 16; ++ks)
                ldmx4(aL[ks][0], aL[ks][1], aL[ks][2], aL[ks][3], aAddr + ks * 32);
        }
        __syncthreads();
    }

    // zero both h buffers
    for (int i = blk * GRU_THREADS + tid; i < 2 * Bq * Dq;
         i += GRU_NBLK * GRU_THREADS) {
        ((__nv_bfloat16 *)g_hhi)[i] = __float2bfloat16(0.f);
        ((__nv_bfloat16 *)g_hlo)[i] = __float2bfloat16(0.f);
    }

    unsigned gen = *(volatile unsigned *)&g_gen2;   // quiescent base (race-free)
    gbar(blk, tid, gen);
    const int x64 = g_x_is64;

    // activation constants (thread -> (dd = tid>>5, b = tid&31))
    const int ab = tid & 31;
    const int ad = tid >> 5;
    const int dglob = d0 + ad;
    const float bh_r = __ldg(bhh + dglob);
    const float bh_z = __ldg(bhh + Dq + dglob);
    const float bh_n = __ldg(bhh + 2 * Dq + dglob);
    float hold = 0.f;

    // B ldmatrix lane pieces
    const int bRow = ((lane >> 4) & 1) * 8 + (lane & 7);
    const int bCol = ((lane >> 3) & 1) * 16;
    const uint32_t bBase = (uint32_t)kq * 512 + (uint32_t)bCol;

    for (int t = 0; t < Tq; ++t) {
        const __nv_bfloat16 *hinH = g_hhi[t & 1];
        const __nv_bfloat16 *hinL = g_hlo[t & 1];
        __nv_bfloat16 *houtH = g_hhi[(t + 1) & 1];
        __nv_bfloat16 *houtL = g_hlo[(t + 1) & 1];

        // prefetch input gates early (hidden under staging + MMA)
        float xr, xz, xn;
        {
            size_t xb;
            if (tokens) {
                int tok;
                if (x64) tok = (int)(((const long long *)tokens)[ab * Tq + t]);
                else     tok = ((const int *)tokens)[ab * Tq + t];
                xb = (size_t)tok * G3 + dglob;
            } else {
                xb = ((size_t)ab * Tq + t) * G3 + dglob;
            }
            xr = __ldg(xgv + xb);
            xz = __ldg(xgv + xb + Dq);
            xn = __ldg(xgv + xb + 2 * Dq);
        }

        // ---- stage full h (bf16 hi/lo) into smem ----
#pragma unroll
        for (int j = 0; j < 16; ++j) {
            int idx = tid + j * GRU_THREADS;     // 0..4095
            int row = idx >> 7;
            int c = idx & 127;
            uint4 vh = __ldcg((const uint4 *)(hinH + row * Dq + c * 8));
            uint4 vl = __ldcg((const uint4 *)(hinL + row * Dq + c * 8));
            *(uint4 *)(sB_hi + row * ROWB + c * 16) = vh;
            *(uint4 *)(sB_lo + row * ROWB + c * 16) = vl;
        }
        __syncthreads();

        // ---- per-warp 32x32x256 split-bf16 HMMA (3 passes) ----
        float acc[4][4];
#pragma unroll
        for (int nt = 0; nt < 4; ++nt)
#pragma unroll
            for (int j = 0; j < 4; ++j) acc[nt][j] = 0.f;

#pragma unroll
        for (int ks = 0; ks < 16; ++ks) {
            uint32_t bh[8], bl[8];
#pragma unroll
            for (int pair = 0; pair < 2; ++pair) {
                uint32_t ba = (uint32_t)((pair * 16 + bRow) * ROWB) + bBase + ks * 32;
                ldmx4(bh[pair * 4 + 0], bh[pair * 4 + 1],
                      bh[pair * 4 + 2], bh[pair * 4 + 3], sBhiA + ba);
                ldmx4(bl[pair * 4 + 0], bl[pair * 4 + 1],
                      bl[pair * 4 + 2], bl[pair * 4 + 3], sBloA + ba);
            }
#pragma unroll
            for (int nt = 0; nt < 4; ++nt) {
                const int ib = nt * 2;
                mma_bf16(acc[nt][0], acc[nt][1], acc[nt][2], acc[nt][3],
                         aH[ks][0], aH[ks][1], aH[ks][2], aH[ks][3],
                         bh[ib], bh[ib + 1]);
                mma_bf16(acc[nt][0], acc[nt][1], acc[nt][2], acc[nt][3],
                         aH[ks][0], aH[ks][1], aH[ks][2], aH[ks][3],
                         bl[ib], bl[ib + 1]);
                mma_bf16(acc[nt][0], acc[nt][1], acc[nt][2], acc[nt][3],
                         aL[ks][0], aL[ks][1], aL[ks][2], aL[ks][3],
                         bh[ib], bh[ib + 1]);
            }
        }

        // ---- intra-CTA k-reduction staging ----
        {
            float *rb = red + (size_t)((kq * 2 + rg) * 16 + (lane >> 2)) * 32;
#pragma unroll
            for (int nt = 0; nt < 4; ++nt) {
                const int b = nt * 8 + (lane & 3) * 2;
                float2 v0, v1;
                v0.x = acc[nt][0]; v0.y = acc[nt][1];
                v1.x = acc[nt][2]; v1.y = acc[nt][3];
                *(float2 *)(rb + b) = v0;
                *(float2 *)(rb + 8 * 32 + b) = v1;
            }
        }
        __syncthreads();

        // ---- fused activation (one elem per thread) ----
        {
            float hr = 0.f, hz = 0.f, hn = 0.f;
#pragma unroll
            for (int q = 0; q < 4; ++q) {
                hr += red[((q * 2 + 0) * 16 + ad) * 32 + ab];
                hz += red[((q * 2 + 0) * 16 + 8 + ad) * 32 + ab];
                hn += red[((q * 2 + 1) * 16 + ad) * 32 + ab];
            }
            hr += bh_r; hz += bh_z; hn += bh_n;
            float r = 1.f / (1.f + expf(-(xr + hr)));
            float z = 1.f / (1.f + expf(-(xz + hz)));
            float n = tanhf(xn + r * hn);
            float hnew = (1.f - z) * n + z * hold;
            hold = hnew;
            __nv_bfloat16 hh = __float2bfloat16(hnew);
            houtH[ab * Dq + dglob] = hh;
            houtL[ab * Dq + dglob] = __float2bfloat16(hnew - __bfloat162float(hh));
            outp[((size_t)ab * Tq + t) * Dq + dglob] = hnew;
        }
        gbar(blk, tid, gen);
    }
}

// ---------------------------------------------------------------------------
// LayerNorm over last dim (1024), one block per row
// ---------------------------------------------------------------------------
__global__ __launch_bounds__(256) void ln_kernel(const float * __restrict__ in,
                                                 float * __restrict__ outp,
                                                 const float * __restrict__ gamma,
                                                 const float * __restrict__ beta) {
    __shared__ float red[2][8];
    const int row = blockIdx.x;
    const int tid = threadIdx.x;
    float4 x = *(const float4 *)&in[(size_t)row * Dq + tid * 4];
    float s = x.x + x.y + x.z + x.w;
    float q = x.x * x.x + x.y * x.y + x.z * x.z + x.w * x.w;
#pragma unroll
    for (int off = 16; off; off >>= 1) {
        s += __shfl_xor_sync(0xffffffffu, s, off);
        q += __shfl_xor_sync(0xffffffffu, q, off);
    }
    if ((tid & 31) == 0) { red[0][tid >> 5] = s; red[1][tid >> 5] = q; }
    __syncthreads();
    if (tid < 32) {
        float ss = (tid < 8) ? red[0][tid] : 0.f;
        float qq = (tid < 8) ? red[1][tid] : 0.f;
#pragma unroll
        for (int off = 4; off; off >>= 1) {
            ss += __shfl_xor_sync(0xffffffffu, ss, off);
            qq += __shfl_xor_sync(0xffffffffu, qq, off);
        }
        if (tid == 0) { red[0][0] = ss; red[1][0] = qq; }
    }
    __syncthreads();
    const float mean = red[0][0] * (1.f / Dq);
    const float var = red[1][0] * (1.f / Dq) - mean * mean;
    const float inv = rsqrtf(var + 1e-5f);
    float4 g  = *(const float4 *)&gamma[tid * 4];
    float4 be = *(const float4 *)&beta[tid * 4];
    float4 o;
    o.x = (x.x - mean) * inv * g.x + be.x;
    o.y = (x.y - mean) * inv * g.y + be.y;
    o.z = (x.z - mean) * inv * g.z + be.z;
    o.w = (x.w - mean) * inv * g.w + be.w;
    *(float4 *)&outp[(size_t)row * Dq + tid * 4] = o;
}

// ---------------------------------------------------------------------------
// Host driver. Inputs: x, E, Wih, Whh, bih, bhh, gamma, beta. Output f32.
// ---------------------------------------------------------------------------
extern "C" void kernel_launch(void *const *d_in, const int *in_sizes, int n_in,
                              void *d_out, int out_size) {
    (void)in_sizes; (void)n_in; (void)out_size;
    const void  *x     = d_in[0];
    const float *E     = (const float *)d_in[1];
    const float *Wih   = (const float *)d_in[2];
    const float *Whh   = (const float *)d_in[3];
    const float *bih   = (const float *)d_in[4];
    const float *bhh   = (const float *)d_in[5];
    const float *gamma = (const float *)d_in[6];
    const float *beta  = (const float *)d_in[7];
    float *out = (float *)d_out;

    float *act0 = nullptr, *act1 = nullptr, *xg = nullptr, *tab = nullptr;
    cudaGetSymbolAddress((void **)&act0, g_act0);
    cudaGetSymbolAddress((void **)&act1, g_act1);
    cudaGetSymbolAddress((void **)&xg, g_xg);
    cudaGetSymbolAddress((void **)&tab, g_tab);

    cudaFuncSetAttribute(gru_mma, cudaFuncAttributeMaxDynamicSharedMemorySize,
                         GRU_DYN_SMEM);
    cudaFuncSetAttribute(gemm_bf3, cudaFuncAttributeMaxDynamicSharedMemorySize,
                         GM_SMEM);

    detect_kernel<<<1, 32>>>((const unsigned *)x);

    // layer 0: per-vocab gate table + tensor-core scan
    {
        dim3 gt(G3 / 64, Vq / 128);
        gemm_bf3<<<gt, 256, GM_SMEM>>>(E, Wih, bih, tab, Vq, G3, Dq);
    }
    gru_mma<<<GRU_NBLK, GRU_THREADS, GRU_DYN_SMEM>>>(Whh, bhh, tab, x, act1);

    // layer 1: dense input-gate GEMM (bf16 HMMA) + tensor-core scan
    {
        dim3 gx(G3 / 64, Mq / 128);
        gemm_bf3<<<gx, 256, GM_SMEM>>>(act1, Wih + (size_t)G3 * Dq, bih + G3,
                                       xg, Mq, G3, Dq);
    }
    gru_mma<<<GRU_NBLK, GRU_THREADS, GRU_DYN_SMEM>>>(Whh + (size_t)G3 * Dq,
                                                     bhh + G3, xg, nullptr, act0);

    // LayerNorm + tied head (bf16 HMMA)
    ln_kernel<<<Mq, 256>>>(act0, act1, gamma, beta);
    dim3 gh(Vq / 64, Mq / 128);
    gemm_bf3<<<gh, 256, GM_SMEM>>>(act1, E, nullptr, out, Mq, Vq, Dq);
}